// round 10
// baseline (speedup 1.0000x reference)
#include <cuda_runtime.h>
#include <math.h>
#include <float.h>

#define BB    8
#define TT    1024
#define FF    256
#define NH    4
#define DKK   64
#define BHH   32
#define NROWS 8192

// ---------------- scratch ----------------------------------------------------
static __device__ float g_xn[NROWS * FF];
static __device__ float g_q [BHH * TT * DKK];
static __device__ float g_k [BHH * TT * DKK];
static __device__ float g_v [BHH * TT * DKK];
static __device__ float g_s [(size_t)BHH * TT * TT];
static __device__ float g_att[NROWS * FF];
static __device__ float g_sum[2 * BHH * TT];   // per-half, per-(bh,q) exp-sums

// ---------------- helpers -----------------------------------------------------
__device__ __forceinline__ unsigned f2tf(float x) {
    unsigned r; asm("cvt.rna.tf32.f32 %0, %1;" : "=r"(r) : "f"(x)); return r;
}
__device__ __forceinline__ void mma8(float* d, const unsigned* a, const unsigned* b, const float* c) {
    asm volatile("mma.sync.aligned.m16n8k8.row.col.f32.tf32.tf32.f32 "
                 "{%0,%1,%2,%3}, {%4,%5,%6,%7}, {%8,%9}, {%10,%11,%12,%13};"
                 : "=f"(d[0]), "=f"(d[1]), "=f"(d[2]), "=f"(d[3])
                 : "r"(a[0]), "r"(a[1]), "r"(a[2]), "r"(a[3]),
                   "r"(b[0]), "r"(b[1]),
                   "f"(c[0]), "f"(c[1]), "f"(c[2]), "f"(c[3]));
}
__device__ __forceinline__ void cpa16(void* s, const void* g) {
    unsigned a = (unsigned)__cvta_generic_to_shared(s);
    asm volatile("cp.async.cg.shared.global [%0], [%1], 16;" :: "r"(a), "l"(g));
}
__device__ __forceinline__ void cp_commit() { asm volatile("cp.async.commit_group;"); }
template<int N> __device__ __forceinline__ void cp_wait() {
    asm volatile("cp.async.wait_group %0;" :: "n"(N));
}

// ---------------- 1) LayerNorm -----------------------------------------------
__global__ void ln_kernel(const float* __restrict__ x, const float* __restrict__ g,
                          const float* __restrict__ b, float* __restrict__ out)
{
    int row = blockIdx.x;
    int tid = threadIdx.x;
    float v = x[row * FF + tid];
    float s = v, sq = v * v;
    __shared__ float rs[8], rq[8];
    #pragma unroll
    for (int o = 16; o > 0; o >>= 1) {
        s  += __shfl_down_sync(0xffffffffu, s,  o);
        sq += __shfl_down_sync(0xffffffffu, sq, o);
    }
    if ((tid & 31) == 0) { rs[tid >> 5] = s; rq[tid >> 5] = sq; }
    __syncthreads();
    if (tid < 32) {
        float a = (tid < 8) ? rs[tid] : 0.f;
        float c = (tid < 8) ? rq[tid] : 0.f;
        #pragma unroll
        for (int o = 4; o > 0; o >>= 1) {
            a += __shfl_down_sync(0xffffffffu, a, o);
            c += __shfl_down_sync(0xffffffffu, c, o);
        }
        if (tid == 0) { rs[0] = a; rq[0] = c; }
    }
    __syncthreads();
    float mean = rs[0] * (1.f / FF);
    float var  = rq[0] * (1.f / FF) - mean * mean;
    float inv  = rsqrtf(fmaxf(var, 0.f) + 1e-5f);
    out[row * FF + tid] = (v - mean) * inv * g[tid] + b[tid];
}

// ---------------- 2) tf32 GEMM core: 128x64, BK=32, 3-stage cp.async ---------
#define G_STAGE_F (128 * 36 + 32 * 72)

__device__ __forceinline__ void gemm_body(
    const float* __restrict__ A, const float* __restrict__ W,
    const float* __restrict__ bias, float* __restrict__ C, int MODE)
{
    extern __shared__ float gsm[];
    int tid = threadIdx.x, w = tid >> 5, l = tid & 31, g = l >> 2, t4 = l & 3;
    int m0 = blockIdx.y * 128, n0 = blockIdx.x * 64;
    int wm = (w >> 1) * 32, wn = (w & 1) * 32;

    float acc[2][4][4];
    #pragma unroll
    for (int i = 0; i < 2; i++)
        #pragma unroll
        for (int j = 0; j < 4; j++)
            #pragma unroll
            for (int e = 0; e < 4; e++) acc[i][j][e] = 0.f;

    auto load_stage = [&](int s, int k0) {
        float* Ab = gsm + s * G_STAGE_F;
        float* Wb = Ab + 128 * 36;
        #pragma unroll
        for (int j = 0; j < 4; j++) {
            int ch = tid + 256 * j;
            int row = ch >> 3, c = ch & 7;
            cpa16(&Ab[row * 36 + c * 4], A + (size_t)(m0 + row) * FF + k0 + c * 4);
        }
        #pragma unroll
        for (int j = 0; j < 2; j++) {
            int ch = tid + 256 * j;
            int row = ch >> 4, c = ch & 15;
            cpa16(&Wb[row * 72 + c * 4], W + (size_t)(k0 + row) * FF + n0 + c * 4);
        }
        cp_commit();
    };

    load_stage(0, 0);
    load_stage(1, 32);

    for (int it = 0; it < 8; it++) {
        int s = it % 3;
        if (it == 7) cp_wait<0>(); else cp_wait<1>();
        __syncthreads();
        if (it + 2 < 8) load_stage((it + 2) % 3, (it + 2) * 32);
        const float* Ab = gsm + s * G_STAGE_F;
        const float* Wb = Ab + 128 * 36;
        #pragma unroll
        for (int ks = 0; ks < 4; ks++) {
            unsigned af[2][4], bf[4][2];
            #pragma unroll
            for (int mi = 0; mi < 2; mi++) {
                int r = wm + mi * 16;
                af[mi][0] = f2tf(Ab[(r + g    ) * 36 + ks * 8 + t4]);
                af[mi][1] = f2tf(Ab[(r + g + 8) * 36 + ks * 8 + t4]);
                af[mi][2] = f2tf(Ab[(r + g    ) * 36 + ks * 8 + t4 + 4]);
                af[mi][3] = f2tf(Ab[(r + g + 8) * 36 + ks * 8 + t4 + 4]);
            }
            #pragma unroll
            for (int ni = 0; ni < 4; ni++) {
                int c = wn + ni * 8 + g;
                bf[ni][0] = f2tf(Wb[(ks * 8 + t4    ) * 72 + c]);
                bf[ni][1] = f2tf(Wb[(ks * 8 + t4 + 4) * 72 + c]);
            }
            #pragma unroll
            for (int mi = 0; mi < 2; mi++)
                #pragma unroll
                for (int ni = 0; ni < 4; ni++)
                    mma8(acc[mi][ni], af[mi], bf[ni], acc[mi][ni]);
        }
        __syncthreads();
    }

    #pragma unroll
    for (int mi = 0; mi < 2; mi++) {
        #pragma unroll
        for (int ni = 0; ni < 4; ni++) {
            int col = n0 + wn + ni * 8 + 2 * t4;
            float b0 = bias[col], b1 = bias[col + 1];
            int r0 = m0 + wm + mi * 16 + g;
            float2 o0 = make_float2(acc[mi][ni][0] + b0, acc[mi][ni][1] + b1);
            float2 o1 = make_float2(acc[mi][ni][2] + b0, acc[mi][ni][3] + b1);
            if (MODE == 0) {
                int h = col >> 6, d = col & 63;
                int b_ = r0 >> 10, t = r0 & 1023;
                *(float2*)&C[(((size_t)(b_*NH + h) * TT + t) * DKK) + d] = o0;
                int r1 = r0 + 8; b_ = r1 >> 10; t = r1 & 1023;
                *(float2*)&C[(((size_t)(b_*NH + h) * TT + t) * DKK) + d] = o1;
            } else {
                *(float2*)&C[(size_t)r0 * FF + col] = o0;
                *(float2*)&C[(size_t)(r0 + 8) * FF + col] = o1;
            }
        }
    }
}

__global__ void __launch_bounds__(256)
proj3_kernel(const float* __restrict__ Aq, const float* __restrict__ Axn,
             const float* __restrict__ Wq, const float* __restrict__ bq,
             const float* __restrict__ Wk, const float* __restrict__ bk,
             const float* __restrict__ Wv, const float* __restrict__ bv,
             float* __restrict__ Cq, float* __restrict__ Ck, float* __restrict__ Cv)
{
    int z = blockIdx.z;
    const float* A = (z == 0) ? Aq : Axn;
    const float* W = (z == 0) ? Wq : (z == 1) ? Wk : Wv;
    const float* b = (z == 0) ? bq : (z == 1) ? bk : bv;
    float* C       = (z == 0) ? Cq : (z == 1) ? Ck : Cv;
    gemm_body(A, W, b, C, 0);
}

__global__ void __launch_bounds__(256)
gemm_out_kernel(const float* __restrict__ A, const float* __restrict__ W,
                const float* __restrict__ bias, float* __restrict__ C)
{
    gemm_body(A, W, bias, C, 1);
}

// ---------------- 3) tf32 QK^T: 128q x 128t, K=64 ----------------------------
__global__ void __launch_bounds__(256)
qk_tf32(const float* __restrict__ Q, const float* __restrict__ K, float* __restrict__ S)
{
    extern __shared__ float qksm[];
    float* Qs = qksm;             // [128][68]
    float* Ks = qksm + 128 * 68;  // [128][68]
    int tid = threadIdx.x, w = tid >> 5, l = tid & 31, g = l >> 2, t4 = l & 3;
    int bh = blockIdx.z, q0 = blockIdx.y * 128, t0 = blockIdx.x * 128;
    int wm = (w >> 2) * 64, wn = (w & 3) * 32;

    #pragma unroll
    for (int j = 0; j < 8; j++) {
        int ch = tid + 256 * j;
        int row = ch >> 4, c = ch & 15;
        cpa16(&Qs[row * 68 + c * 4], Q + ((size_t)bh * TT + q0 + row) * DKK + c * 4);
    }
    #pragma unroll
    for (int j = 0; j < 8; j++) {
        int ch = tid + 256 * j;
        int row = ch >> 4, c = ch & 15;
        cpa16(&Ks[row * 68 + c * 4], K + ((size_t)bh * TT + t0 + row) * DKK + c * 4);
    }
    cp_commit(); cp_wait<0>();
    __syncthreads();

    float acc[4][4][4];
    #pragma unroll
    for (int i = 0; i < 4; i++)
        #pragma unroll
        for (int j = 0; j < 4; j++)
            #pragma unroll
            for (int e = 0; e < 4; e++) acc[i][j][e] = 0.f;

    #pragma unroll
    for (int ks = 0; ks < 8; ks++) {
        unsigned af[4][4], bf[4][2];
        #pragma unroll
        for (int mi = 0; mi < 4; mi++) {
            int r = wm + mi * 16;
            af[mi][0] = f2tf(Qs[(r + g    ) * 68 + ks * 8 + t4]);
            af[mi][1] = f2tf(Qs[(r + g + 8) * 68 + ks * 8 + t4]);
            af[mi][2] = f2tf(Qs[(r + g    ) * 68 + ks * 8 + t4 + 4]);
            af[mi][3] = f2tf(Qs[(r + g + 8) * 68 + ks * 8 + t4 + 4]);
        }
        #pragma unroll
        for (int ni = 0; ni < 4; ni++) {
            int c = wn + ni * 8 + g;
            bf[ni][0] = f2tf(Ks[c * 68 + ks * 8 + t4]);
            bf[ni][1] = f2tf(Ks[c * 68 + ks * 8 + t4 + 4]);
        }
        #pragma unroll
        for (int mi = 0; mi < 4; mi++)
            #pragma unroll
            for (int ni = 0; ni < 4; ni++)
                mma8(acc[mi][ni], af[mi], bf[ni], acc[mi][ni]);
    }

    float* dst = S + (size_t)bh * TT * TT;
    #pragma unroll
    for (int mi = 0; mi < 4; mi++)
        #pragma unroll
        for (int ni = 0; ni < 4; ni++) {
            int r0 = q0 + wm + mi * 16 + g;
            int col = t0 + wn + ni * 8 + 2 * t4;
            *(float2*)&dst[(size_t)r0 * TT + col] = make_float2(acc[mi][ni][0], acc[mi][ni][1]);
            *(float2*)&dst[(size_t)(r0 + 8) * TT + col] = make_float2(acc[mi][ni][2], acc[mi][ni][3]);
        }
}

// ---------------- 4) one-pass bias + combine + mask + exp (max-free) ---------
// Grid (2 halves, 1024 q), 512 threads, 2 CTAs/SM. 8 chunks of 64 t each,
// 3-stage cp.async pipeline over {pos_k, S, mask}. Writes unnormalized
// exp probs to S and per-(half,bh,q) sums to g_sum; AV normalizes.
#define B_PK_F  (64 * 68)
#define B_SG_F  (32 * 68)
#define B_MK_F  (8 * 68)
#define B_STG_F (B_PK_F + B_SG_F + B_MK_F)   // 7072 floats per stage

__global__ void __launch_bounds__(512, 2)
bsm_kernel(const float* __restrict__ Qg, const float* __restrict__ PK,
           const int* __restrict__ mask, float* __restrict__ S,
           float* __restrict__ gsum)
{
    extern __shared__ float sm[];
    float* Qs   = sm;                      // [32][68]
    float* Stg  = sm + 32 * 68;            // 3 stages
    float* ssum = Stg + 3 * B_STG_F;       // [32]
    int tid = threadIdx.x, w = tid >> 5, l = tid & 31, g = l >> 2, t4 = l & 3;
    int q = blockIdx.y, half = blockIdx.x;
    int tbase = half * 512;
    int wm_ = (w & 1) * 16, wn_ = (w >> 1) * 8;   // 16 warps: 2m x 8n

    if (tid < 256) {
        int bh = tid >> 3, dg = (tid & 7) * 8;
        const float* src = Qg + ((size_t)bh * TT + q) * DKK + dg;
        *(float4*)&Qs[bh * 68 + dg]     = *(const float4*)(src);
        *(float4*)&Qs[bh * 68 + dg + 4] = *(const float4*)(src + 4);
    }
    if (tid < 32) ssum[tid] = 0.f;

    auto load_chunk = [&](int s, int c) {
        int t0 = tbase + c * 64;
        float* Pb = Stg + s * B_STG_F;
        #pragma unroll
        for (int j = 0; j < 2; j++) {          // pos_k: 64 rows x 16 chunks
            int ch = tid + 512 * j;
            int row = ch >> 4, cc = ch & 15;
            cpa16(&Pb[row * 68 + cc * 4], PK + ((size_t)q * TT + t0 + row) * DKK + cc * 4);
        }
        float* Sb = Pb + B_PK_F;
        {                                       // S: 32 bh rows x 16 chunks
            int row = tid >> 4, cc = tid & 15;
            cpa16(&Sb[row * 68 + cc * 4],
                  S + (size_t)row * TT * TT + (size_t)q * TT + t0 + cc * 4);
        }
        int* Mb = (int*)(Sb + B_SG_F);
        if (tid < 128) {                        // mask: 8 batch rows x 16 chunks
            int row = tid >> 4, cc = tid & 15;
            cpa16(&Mb[row * 68 + cc * 4],
                  mask + ((size_t)row * TT + q) * TT + t0 + cc * 4);
        }
        cp_commit();
    };

    load_chunk(0, 0);
    load_chunk(1, 1);
    __syncthreads();   // Qs + ssum visible

    float sum0 = 0.f, sum1 = 0.f;

    for (int c = 0; c < 8; c++) {
        int s = c % 3;
        if (c == 7) cp_wait<0>(); else cp_wait<1>();
        __syncthreads();
        if (c + 2 < 8) load_chunk((c + 2) % 3, c + 2);

        const float* Pb = Stg + s * B_STG_F;
        const float* Sb = Pb + B_PK_F;
        const int*   Mb = (const int*)(Sb + B_SG_F);

        float acc[4] = {0.f, 0.f, 0.f, 0.f};
        #pragma unroll
        for (int ks = 0; ks < 8; ks++) {
            unsigned af[4], bf[2];
            af[0] = f2tf(Qs[(wm_ + g    ) * 68 + ks * 8 + t4]);
            af[1] = f2tf(Qs[(wm_ + g + 8) * 68 + ks * 8 + t4]);
            af[2] = f2tf(Qs[(wm_ + g    ) * 68 + ks * 8 + t4 + 4]);
            af[3] = f2tf(Qs[(wm_ + g + 8) * 68 + ks * 8 + t4 + 4]);
            int cn = wn_ + g;
            bf[0] = f2tf(Pb[cn * 68 + ks * 8 + t4]);
            bf[1] = f2tf(Pb[cn * 68 + ks * 8 + t4 + 4]);
            mma8(acc, af, bf, acc);
        }

        int t0g = tbase + c * 64;
        int colL = wn_ + 2 * t4;
        #pragma unroll
        for (int rr = 0; rr < 2; rr++) {
            int bh = wm_ + g + rr * 8;
            int b_ = bh >> 2;
            int m0 = Mb[b_ * 68 + colL];
            int m1 = Mb[b_ * 68 + colL + 1];
            float v0 = (Sb[bh * 68 + colL]     + acc[rr * 2 + 0]) * 0.125f;
            float v1 = (Sb[bh * 68 + colL + 1] + acc[rr * 2 + 1]) * 0.125f;
            float p0 = (m0 == 0) ? 0.f : __expf(v0);
            float p1 = (m1 == 0) ? 0.f : __expf(v1);
            if (rr == 0) sum0 += p0 + p1; else sum1 += p0 + p1;
            *(float2*)&S[(size_t)bh * TT * TT + (size_t)q * TT + t0g + colL] =
                make_float2(p0, p1);
        }
    }

    // reduce sums: quad (t4) shuffle, then smem atomics over 32 rows
    #pragma unroll
    for (int o = 1; o <= 2; o <<= 1) {
        sum0 += __shfl_xor_sync(0xffffffffu, sum0, o);
        sum1 += __shfl_xor_sync(0xffffffffu, sum1, o);
    }
    if (t4 == 0) {
        atomicAdd(&ssum[wm_ + g],     sum0);
        atomicAdd(&ssum[wm_ + g + 8], sum1);
    }
    __syncthreads();
    if (tid < 32)
        gsum[((size_t)half * BHH + tid) * TT + q] = ssum[tid];
}

// ---------------- 5) tf32 AV: 256q x 64d, 512 threads, + normalization -------
__global__ void __launch_bounds__(512)
av_tf32(const float* __restrict__ P, const float* __restrict__ V,
        const float* __restrict__ gsum, float* __restrict__ O)
{
    extern __shared__ float avsm[];
    float* Ps = avsm;                  // [2][256][68]
    float* Vs = avsm + 2 * 256 * 68;   // [2][64][72]
    int tid = threadIdx.x, w = tid >> 5, l = tid & 31, g = l >> 2, t4 = l & 3;
    int q0 = blockIdx.x * 256;
    int bh = blockIdx.y, b_ = bh >> 2, h = bh & 3;
    int wm = (w >> 1) * 32, wn = (w & 1) * 32;

    float acc[2][4][4];
    #pragma unroll
    for (int i = 0; i < 2; i++)
        #pragma unroll
        for (int j = 0; j < 4; j++)
            #pragma unroll
            for (int e = 0; e < 4; e++) acc[i][j][e] = 0.f;

    const float* Pb_g = P + (size_t)bh * TT * TT;
    const float* Vb_g = V + (size_t)bh * TT * DKK;

    auto load_stage = [&](int buf, int t0) {
        float* Pd = Ps + buf * 256 * 68;
        #pragma unroll
        for (int j = 0; j < 8; j++) {
            int ch = tid + 512 * j;
            int row = ch >> 4, c = ch & 15;
            cpa16(&Pd[row * 68 + c * 4], Pb_g + (size_t)(q0 + row) * TT + t0 + c * 4);
        }
        float* Vd = Vs + buf * 64 * 72;
        #pragma unroll
        for (int j = 0; j < 2; j++) {
            int ch = tid + 512 * j;
            int row = ch >> 4, c = ch & 15;
            cpa16(&Vd[row * 72 + c * 4], Vb_g + (size_t)(t0 + row) * DKK + c * 4);
        }
        cp_commit();
    };

    load_stage(0, 0);

    for (int it = 0; it < 16; it++) {
        int buf = it & 1;
        cp_wait<0>();
        __syncthreads();
        if (it + 1 < 16) load_stage(buf ^ 1, (it + 1) * 64);
        const float* Pd = Ps + buf * 256 * 68;
        const float* Vd = Vs + buf * 64 * 72;
        #pragma unroll
        for (int ks = 0; ks < 8; ks++) {
            unsigned af[2][4], bf[4][2];
            #pragma unroll
            for (int mi = 0; mi < 2; mi++) {
                int r = wm + mi * 16;
                af[mi][0] = f2tf(Pd[(r + g    ) * 68 + ks * 8 + t4]);
                af[mi][1] = f2tf(Pd[(r + g + 8) * 68 + ks * 8 + t4]);
                af[mi][2] = f2tf(Pd[(r + g    ) * 68 + ks * 8 + t4 + 4]);
                af[mi][3] = f2tf(Pd[(r + g + 8) * 68 + ks * 8 + t4 + 4]);
            }
            #pragma unroll
            for (int ni = 0; ni < 4; ni++) {
                int c = wn + ni * 8 + g;
                bf[ni][0] = f2tf(Vd[(ks * 8 + t4    ) * 72 + c]);
                bf[ni][1] = f2tf(Vd[(ks * 8 + t4 + 4) * 72 + c]);
            }
            #pragma unroll
            for (int mi = 0; mi < 2; mi++)
                #pragma unroll
                for (int ni = 0; ni < 4; ni++)
                    mma8(acc[mi][ni], af[mi], bf[ni], acc[mi][ni]);
        }
        __syncthreads();
    }

    #pragma unroll
    for (int mi = 0; mi < 2; mi++) {
        int qq = q0 + wm + mi * 16 + g;
        float sA = gsum[(size_t)bh * TT + qq] + gsum[((size_t)BHH + bh) * TT + qq];
        float sB = gsum[(size_t)bh * TT + qq + 8] + gsum[((size_t)BHH + bh) * TT + qq + 8];
        float invA = (sA > 0.f) ? (1.f / sA) : 0.f;
        float invB = (sB > 0.f) ? (1.f / sB) : 0.f;
        #pragma unroll
        for (int ni = 0; ni < 4; ni++) {
            int d = wn + ni * 8 + 2 * t4;
            *(float2*)&O[((size_t)b_ * TT + qq) * FF + h * DKK + d] =
                make_float2(acc[mi][ni][0] * invA, acc[mi][ni][1] * invA);
            *(float2*)&O[((size_t)b_ * TT + qq + 8) * FF + h * DKK + d] =
                make_float2(acc[mi][ni][2] * invB, acc[mi][ni][3] * invB);
        }
    }
}

// ---------------- launch ------------------------------------------------------
extern "C" void kernel_launch(void* const* d_in, const int* in_sizes, int n_in,
                              void* d_out, int out_size)
{
    (void)in_sizes; (void)n_in; (void)out_size;
    const float* x     = (const float*)d_in[0];
    const float* q_in  = (const float*)d_in[1];
    const float* pos_k = (const float*)d_in[2];
    const int*   mask  = (const int*)  d_in[3];
    const float* ln_g  = (const float*)d_in[4];
    const float* ln_b  = (const float*)d_in[5];
    const float* Wq    = (const float*)d_in[6];
    const float* bq    = (const float*)d_in[7];
    const float* Wk    = (const float*)d_in[8];
    const float* bk    = (const float*)d_in[9];
    const float* Wv    = (const float*)d_in[10];
    const float* bv    = (const float*)d_in[11];
    const float* Wo    = (const float*)d_in[12];
    const float* bo    = (const float*)d_in[13];
    float* out = (float*)d_out;

    float *p_xn, *p_q, *p_k, *p_v, *p_s, *p_att, *p_sum;
    cudaGetSymbolAddress((void**)&p_xn,  g_xn);
    cudaGetSymbolAddress((void**)&p_q,   g_q);
    cudaGetSymbolAddress((void**)&p_k,   g_k);
    cudaGetSymbolAddress((void**)&p_v,   g_v);
    cudaGetSymbolAddress((void**)&p_s,   g_s);
    cudaGetSymbolAddress((void**)&p_att, g_att);
    cudaGetSymbolAddress((void**)&p_sum, g_sum);

    static const int GEMM_SMEM = 3 * G_STAGE_F * 4;
    static const int QK_SMEM   = 2 * 128 * 68 * 4;
    static const int BSM_SMEM  = (32 * 68 + 3 * B_STG_F + 32) * 4;   // 93824
    static const int AV_SMEM   = (2 * 256 * 68 + 2 * 64 * 72) * 4;   // 176128
    cudaFuncSetAttribute(proj3_kernel,    cudaFuncAttributeMaxDynamicSharedMemorySize, GEMM_SMEM);
    cudaFuncSetAttribute(gemm_out_kernel, cudaFuncAttributeMaxDynamicSharedMemorySize, GEMM_SMEM);
    cudaFuncSetAttribute(qk_tf32,         cudaFuncAttributeMaxDynamicSharedMemorySize, QK_SMEM);
    cudaFuncSetAttribute(bsm_kernel,      cudaFuncAttributeMaxDynamicSharedMemorySize, BSM_SMEM);
    cudaFuncSetAttribute(av_tf32,         cudaFuncAttributeMaxDynamicSharedMemorySize, AV_SMEM);

    ln_kernel<<<NROWS, 256>>>(x, ln_g, ln_b, p_xn);

    dim3 gproj(FF / 64, NROWS / 128, 3);
    proj3_kernel<<<gproj, 256, GEMM_SMEM>>>(q_in, p_xn, Wq, bq, Wk, bk, Wv, bv,
                                            p_q, p_k, p_v);

    dim3 gqk(TT / 128, TT / 128, BHH);
    qk_tf32<<<gqk, 256, QK_SMEM>>>(p_q, p_k, p_s);

    dim3 gbsm(2, TT);
    bsm_kernel<<<gbsm, 512, BSM_SMEM>>>(p_q, pos_k, mask, p_s, p_sum);

    dim3 gav(TT / 256, BHH);
    av_tf32<<<gav, 512, AV_SMEM>>>(p_s, p_v, p_sum, p_att);

    dim3 gout(FF / 64, NROWS / 128);
    gemm_out_kernel<<<gout, 256, GEMM_SMEM>>>(p_att, Wo, bo, out);
}

// round 11
// speedup vs baseline: 1.2533x; 1.2533x over previous
#include <cuda_runtime.h>
#include <math.h>
#include <float.h>

#define BB    8
#define TT    1024
#define FF    256
#define NH    4
#define DKK   64
#define BHH   32
#define NROWS 8192

#define SSTR  1028   // Ss row stride in floats; 1028*4=4112 B, 16B-aligned

// ---------------- scratch ----------------------------------------------------
static __device__ float g_xn[NROWS * FF];
static __device__ float g_q [BHH * TT * DKK];
static __device__ float g_k [BHH * TT * DKK];
static __device__ float g_v [BHH * TT * DKK];
static __device__ float g_s [(size_t)BHH * TT * TT];
static __device__ float g_att[NROWS * FF];

// ---------------- helpers -----------------------------------------------------
__device__ __forceinline__ unsigned f2tf(float x) {
    unsigned r; asm("cvt.rna.tf32.f32 %0, %1;" : "=r"(r) : "f"(x)); return r;
}
__device__ __forceinline__ void mma8(float* d, const unsigned* a, const unsigned* b, const float* c) {
    asm volatile("mma.sync.aligned.m16n8k8.row.col.f32.tf32.tf32.f32 "
                 "{%0,%1,%2,%3}, {%4,%5,%6,%7}, {%8,%9}, {%10,%11,%12,%13};"
                 : "=f"(d[0]), "=f"(d[1]), "=f"(d[2]), "=f"(d[3])
                 : "r"(a[0]), "r"(a[1]), "r"(a[2]), "r"(a[3]),
                   "r"(b[0]), "r"(b[1]),
                   "f"(c[0]), "f"(c[1]), "f"(c[2]), "f"(c[3]));
}
__device__ __forceinline__ void cpa16(void* s, const void* g) {
    unsigned a = (unsigned)__cvta_generic_to_shared(s);
    asm volatile("cp.async.cg.shared.global [%0], [%1], 16;" :: "r"(a), "l"(g));
}
__device__ __forceinline__ void cp_commit() { asm volatile("cp.async.commit_group;"); }
template<int N> __device__ __forceinline__ void cp_wait() {
    asm volatile("cp.async.wait_group %0;" :: "n"(N));
}

// ---------------- 1) LayerNorm -----------------------------------------------
__global__ void ln_kernel(const float* __restrict__ x, const float* __restrict__ g,
                          const float* __restrict__ b, float* __restrict__ out)
{
    int row = blockIdx.x;
    int tid = threadIdx.x;
    float v = x[row * FF + tid];
    float s = v, sq = v * v;
    __shared__ float rs[8], rq[8];
    #pragma unroll
    for (int o = 16; o > 0; o >>= 1) {
        s  += __shfl_down_sync(0xffffffffu, s,  o);
        sq += __shfl_down_sync(0xffffffffu, sq, o);
    }
    if ((tid & 31) == 0) { rs[tid >> 5] = s; rq[tid >> 5] = sq; }
    __syncthreads();
    if (tid < 32) {
        float a = (tid < 8) ? rs[tid] : 0.f;
        float c = (tid < 8) ? rq[tid] : 0.f;
        #pragma unroll
        for (int o = 4; o > 0; o >>= 1) {
            a += __shfl_down_sync(0xffffffffu, a, o);
            c += __shfl_down_sync(0xffffffffu, c, o);
        }
        if (tid == 0) { rs[0] = a; rq[0] = c; }
    }
    __syncthreads();
    float mean = rs[0] * (1.f / FF);
    float var  = rq[0] * (1.f / FF) - mean * mean;
    float inv  = rsqrtf(fmaxf(var, 0.f) + 1e-5f);
    out[row * FF + tid] = (v - mean) * inv * g[tid] + b[tid];
}

// ---------------- 2) tf32 GEMM core: 128x64, BK=32, 3-stage cp.async ---------
#define G_STAGE_F (128 * 36 + 32 * 72)

__device__ __forceinline__ void gemm_body(
    const float* __restrict__ A, const float* __restrict__ W,
    const float* __restrict__ bias, float* __restrict__ C, int MODE)
{
    extern __shared__ float gsm[];
    int tid = threadIdx.x, w = tid >> 5, l = tid & 31, g = l >> 2, t4 = l & 3;
    int m0 = blockIdx.y * 128, n0 = blockIdx.x * 64;
    int wm = (w >> 1) * 32, wn = (w & 1) * 32;

    float acc[2][4][4];
    #pragma unroll
    for (int i = 0; i < 2; i++)
        #pragma unroll
        for (int j = 0; j < 4; j++)
            #pragma unroll
            for (int e = 0; e < 4; e++) acc[i][j][e] = 0.f;

    auto load_stage = [&](int s, int k0) {
        float* Ab = gsm + s * G_STAGE_F;
        float* Wb = Ab + 128 * 36;
        #pragma unroll
        for (int j = 0; j < 4; j++) {
            int ch = tid + 256 * j;
            int row = ch >> 3, c = ch & 7;
            cpa16(&Ab[row * 36 + c * 4], A + (size_t)(m0 + row) * FF + k0 + c * 4);
        }
        #pragma unroll
        for (int j = 0; j < 2; j++) {
            int ch = tid + 256 * j;
            int row = ch >> 4, c = ch & 15;
            cpa16(&Wb[row * 72 + c * 4], W + (size_t)(k0 + row) * FF + n0 + c * 4);
        }
        cp_commit();
    };

    load_stage(0, 0);
    load_stage(1, 32);

    for (int it = 0; it < 8; it++) {
        int s = it % 3;
        if (it == 7) cp_wait<0>(); else cp_wait<1>();
        __syncthreads();
        if (it + 2 < 8) load_stage((it + 2) % 3, (it + 2) * 32);
        const float* Ab = gsm + s * G_STAGE_F;
        const float* Wb = Ab + 128 * 36;
        #pragma unroll
        for (int ks = 0; ks < 4; ks++) {
            unsigned af[2][4], bf[4][2];
            #pragma unroll
            for (int mi = 0; mi < 2; mi++) {
                int r = wm + mi * 16;
                af[mi][0] = f2tf(Ab[(r + g    ) * 36 + ks * 8 + t4]);
                af[mi][1] = f2tf(Ab[(r + g + 8) * 36 + ks * 8 + t4]);
                af[mi][2] = f2tf(Ab[(r + g    ) * 36 + ks * 8 + t4 + 4]);
                af[mi][3] = f2tf(Ab[(r + g + 8) * 36 + ks * 8 + t4 + 4]);
            }
            #pragma unroll
            for (int ni = 0; ni < 4; ni++) {
                int c = wn + ni * 8 + g;
                bf[ni][0] = f2tf(Wb[(ks * 8 + t4    ) * 72 + c]);
                bf[ni][1] = f2tf(Wb[(ks * 8 + t4 + 4) * 72 + c]);
            }
            #pragma unroll
            for (int mi = 0; mi < 2; mi++)
                #pragma unroll
                for (int ni = 0; ni < 4; ni++)
                    mma8(acc[mi][ni], af[mi], bf[ni], acc[mi][ni]);
        }
        __syncthreads();
    }

    #pragma unroll
    for (int mi = 0; mi < 2; mi++) {
        #pragma unroll
        for (int ni = 0; ni < 4; ni++) {
            int col = n0 + wn + ni * 8 + 2 * t4;
            float b0 = bias[col], b1 = bias[col + 1];
            int r0 = m0 + wm + mi * 16 + g;
            float2 o0 = make_float2(acc[mi][ni][0] + b0, acc[mi][ni][1] + b1);
            float2 o1 = make_float2(acc[mi][ni][2] + b0, acc[mi][ni][3] + b1);
            if (MODE == 0) {
                int h = col >> 6, d = col & 63;
                int b_ = r0 >> 10, t = r0 & 1023;
                *(float2*)&C[(((size_t)(b_*NH + h) * TT + t) * DKK) + d] = o0;
                int r1 = r0 + 8; b_ = r1 >> 10; t = r1 & 1023;
                *(float2*)&C[(((size_t)(b_*NH + h) * TT + t) * DKK) + d] = o1;
            } else {
                *(float2*)&C[(size_t)r0 * FF + col] = o0;
                *(float2*)&C[(size_t)(r0 + 8) * FF + col] = o1;
            }
        }
    }
}

__global__ void __launch_bounds__(256)
proj3_kernel(const float* __restrict__ Aq, const float* __restrict__ Axn,
             const float* __restrict__ Wq, const float* __restrict__ bq,
             const float* __restrict__ Wk, const float* __restrict__ bk,
             const float* __restrict__ Wv, const float* __restrict__ bv,
             float* __restrict__ Cq, float* __restrict__ Ck, float* __restrict__ Cv)
{
    int z = blockIdx.z;
    const float* A = (z == 0) ? Aq : Axn;
    const float* W = (z == 0) ? Wq : (z == 1) ? Wk : Wv;
    const float* b = (z == 0) ? bq : (z == 1) ? bk : bv;
    float* C       = (z == 0) ? Cq : (z == 1) ? Ck : Cv;
    gemm_body(A, W, b, C, 0);
}

__global__ void __launch_bounds__(256)
gemm_out_kernel(const float* __restrict__ A, const float* __restrict__ W,
                const float* __restrict__ bias, float* __restrict__ C)
{
    gemm_body(A, W, bias, C, 1);
}

// ---------------- 3) tf32 QK^T: 128q x 128t, K=64 ----------------------------
__global__ void __launch_bounds__(256)
qk_tf32(const float* __restrict__ Q, const float* __restrict__ K, float* __restrict__ S)
{
    extern __shared__ float qksm[];
    float* Qs = qksm;             // [128][68]
    float* Ks = qksm + 128 * 68;  // [128][68]
    int tid = threadIdx.x, w = tid >> 5, l = tid & 31, g = l >> 2, t4 = l & 3;
    int bh = blockIdx.z, q0 = blockIdx.y * 128, t0 = blockIdx.x * 128;
    int wm = (w >> 2) * 64, wn = (w & 3) * 32;

    #pragma unroll
    for (int j = 0; j < 8; j++) {
        int ch = tid + 256 * j;
        int row = ch >> 4, c = ch & 15;
        cpa16(&Qs[row * 68 + c * 4], Q + ((size_t)bh * TT + q0 + row) * DKK + c * 4);
    }
    #pragma unroll
    for (int j = 0; j < 8; j++) {
        int ch = tid + 256 * j;
        int row = ch >> 4, c = ch & 15;
        cpa16(&Ks[row * 68 + c * 4], K + ((size_t)bh * TT + t0 + row) * DKK + c * 4);
    }
    cp_commit(); cp_wait<0>();
    __syncthreads();

    float acc[4][4][4];
    #pragma unroll
    for (int i = 0; i < 4; i++)
        #pragma unroll
        for (int j = 0; j < 4; j++)
            #pragma unroll
            for (int e = 0; e < 4; e++) acc[i][j][e] = 0.f;

    #pragma unroll
    for (int ks = 0; ks < 8; ks++) {
        unsigned af[4][4], bf[4][2];
        #pragma unroll
        for (int mi = 0; mi < 4; mi++) {
            int r = wm + mi * 16;
            af[mi][0] = f2tf(Qs[(r + g    ) * 68 + ks * 8 + t4]);
            af[mi][1] = f2tf(Qs[(r + g + 8) * 68 + ks * 8 + t4]);
            af[mi][2] = f2tf(Qs[(r + g    ) * 68 + ks * 8 + t4 + 4]);
            af[mi][3] = f2tf(Qs[(r + g + 8) * 68 + ks * 8 + t4 + 4]);
        }
        #pragma unroll
        for (int ni = 0; ni < 4; ni++) {
            int c = wn + ni * 8 + g;
            bf[ni][0] = f2tf(Ks[c * 68 + ks * 8 + t4]);
            bf[ni][1] = f2tf(Ks[c * 68 + ks * 8 + t4 + 4]);
        }
        #pragma unroll
        for (int mi = 0; mi < 4; mi++)
            #pragma unroll
            for (int ni = 0; ni < 4; ni++)
                mma8(acc[mi][ni], af[mi], bf[ni], acc[mi][ni]);
    }

    float* dst = S + (size_t)bh * TT * TT;
    #pragma unroll
    for (int mi = 0; mi < 4; mi++)
        #pragma unroll
        for (int ni = 0; ni < 4; ni++) {
            int r0 = q0 + wm + mi * 16 + g;
            int col = t0 + wn + ni * 8 + 2 * t4;
            *(float2*)&dst[(size_t)r0 * TT + col] = make_float2(acc[mi][ni][0], acc[mi][ni][1]);
            *(float2*)&dst[(size_t)(r0 + 8) * TT + col] = make_float2(acc[mi][ni][2], acc[mi][ni][3]);
        }
}

// ---------------- 4) fused bias + mask + softmax (R5 structure, fixed) -------
// CTA per q, 512 threads. Phase 1: 16 chunks of 64 t, cp.async double-buffered
// pos_k, bias mma into Ss. Mask preloaded to smem (overlapped with chunk 0).
// Phase 2: vectorized combine (coalesced S float4, smem mask/bias), softmax.
__global__ void __launch_bounds__(512)
bsm_kernel(const float* __restrict__ Qg, const float* __restrict__ PK,
           const int* __restrict__ mask, float* __restrict__ S)
{
    extern __shared__ float sm[];
    float* Ss = sm;                          // [32][SSTR]   131.6 KB
    float* Qs = Ss + 32 * SSTR;              // [32][68]       8.7 KB
    int*   Mk = (int*)(Qs + 32 * 68);        // [8][1024]     32   KB
    float* Ps = (float*)(Mk + 8 * 1024);     // [2][64][68]   34.8 KB
    int tid = threadIdx.x, w = tid >> 5, l = tid & 31, g = l >> 2, t4 = l & 3;
    int q = blockIdx.x;
    int wm_ = (w & 1) * 16, wn_ = (w >> 1) * 8;   // 16 warps: 2m x 8n over 64 t

    if (tid < 256) {
        int bh = tid >> 3, dg = (tid & 7) * 8;
        const float* src = Qg + ((size_t)bh * TT + q) * DKK + dg;
        *(float4*)&Qs[bh * 68 + dg]     = *(const float4*)(src);
        *(float4*)&Qs[bh * 68 + dg + 4] = *(const float4*)(src + 4);
    }
    // mask -> smem (all 8 batches), overlapped with phase-1 chunk 0
    #pragma unroll
    for (int j = 0; j < 4; j++) {
        int ch = tid + 512 * j;              // 2048 int4 chunks
        int b_ = ch >> 8, t = (ch & 255) * 4;
        cpa16(&Mk[b_ * 1024 + t], mask + ((size_t)b_ * TT + q) * TT + t);
    }

    auto load_chunk = [&](int buf, int c) {
        int t0 = c * 64;
        float* Pb = Ps + buf * 64 * 68;
        #pragma unroll
        for (int j = 0; j < 2; j++) {        // pos_k: 64 rows x 16 chunks
            int ch = tid + 512 * j;
            int row = ch >> 4, cc = ch & 15;
            cpa16(&Pb[row * 68 + cc * 4], PK + ((size_t)q * TT + t0 + row) * DKK + cc * 4);
        }
        cp_commit();
    };

    load_chunk(0, 0);                        // (mask rides in this first group)
    __syncthreads();                         // Qs visible

    for (int c = 0; c < 16; c++) {
        int buf = c & 1;
        cp_wait<0>();
        __syncthreads();
        if (c + 1 < 16) load_chunk(buf ^ 1, c + 1);
        const float* Pb = Ps + buf * 64 * 68;

        float acc[4] = {0.f, 0.f, 0.f, 0.f};
        #pragma unroll
        for (int ks = 0; ks < 8; ks++) {
            unsigned af[4], bf[2];
            af[0] = f2tf(Qs[(wm_ + g    ) * 68 + ks * 8 + t4]);
            af[1] = f2tf(Qs[(wm_ + g + 8) * 68 + ks * 8 + t4]);
            af[2] = f2tf(Qs[(wm_ + g    ) * 68 + ks * 8 + t4 + 4]);
            af[3] = f2tf(Qs[(wm_ + g + 8) * 68 + ks * 8 + t4 + 4]);
            int cn = wn_ + g;
            bf[0] = f2tf(Pb[cn * 68 + ks * 8 + t4]);
            bf[1] = f2tf(Pb[cn * 68 + ks * 8 + t4 + 4]);
            mma8(acc, af, bf, acc);
        }
        int t0 = c * 64;
        int colL = wn_ + 2 * t4;
        #pragma unroll
        for (int rr = 0; rr < 2; rr++) {
            int bh = wm_ + g + rr * 8;
            *(float2*)&Ss[bh * SSTR + t0 + colL] =
                make_float2(acc[rr * 2], acc[rr * 2 + 1]);
        }
        __syncthreads();
    }

    // ---- phase 2: combine + mask + scale + softmax; warp w owns bh=2w,2w+1 --
    #pragma unroll
    for (int bb = 0; bb < 2; bb++) {
        int bh = w * 2 + bb;
        int b_ = bh >> 2;
        float* srow = S + (size_t)bh * TT * TT + (size_t)q * TT;
        float* ssr  = Ss + bh * SSTR;
        const int* mkr = Mk + b_ * 1024;

        float mx = -FLT_MAX;
        #pragma unroll
        for (int i = 0; i < 8; i++) {
            int t = 4 * (l + 32 * i);
            float4 sv = *(const float4*)&srow[t];      // coalesced global
            int4   mv = *(const int4*)&mkr[t];         // smem
            float4 bv = *(const float4*)&ssr[t];       // smem (bias)
            float4 o;
            o.x = (mv.x == 0) ? -FLT_MAX : (sv.x + bv.x) * 0.125f;
            o.y = (mv.y == 0) ? -FLT_MAX : (sv.y + bv.y) * 0.125f;
            o.z = (mv.z == 0) ? -FLT_MAX : (sv.z + bv.z) * 0.125f;
            o.w = (mv.w == 0) ? -FLT_MAX : (sv.w + bv.w) * 0.125f;
            *(float4*)&ssr[t] = o;
            mx = fmaxf(mx, fmaxf(fmaxf(o.x, o.y), fmaxf(o.z, o.w)));
        }
        #pragma unroll
        for (int o = 16; o > 0; o >>= 1)
            mx = fmaxf(mx, __shfl_xor_sync(0xffffffffu, mx, o));

        float sum = 0.f;
        #pragma unroll
        for (int i = 0; i < 8; i++) {
            int t = 4 * (l + 32 * i);
            float4 v = *(const float4*)&ssr[t];
            float4 p;
            p.x = (v.x == -FLT_MAX) ? 0.f : __expf(v.x - mx);
            p.y = (v.y == -FLT_MAX) ? 0.f : __expf(v.y - mx);
            p.z = (v.z == -FLT_MAX) ? 0.f : __expf(v.z - mx);
            p.w = (v.w == -FLT_MAX) ? 0.f : __expf(v.w - mx);
            *(float4*)&ssr[t] = p;
            sum += p.x + p.y + p.z + p.w;
        }
        #pragma unroll
        for (int o = 16; o > 0; o >>= 1)
            sum += __shfl_xor_sync(0xffffffffu, sum, o);
        float inv = (sum > 0.f) ? (1.f / sum) : 0.f;

        #pragma unroll
        for (int i = 0; i < 8; i++) {
            int t = 4 * (l + 32 * i);
            float4 v = *(const float4*)&ssr[t];
            float4 o;
            o.x = v.x * inv; o.y = v.y * inv; o.z = v.z * inv; o.w = v.w * inv;
            *(float4*)&srow[t] = o;                    // coalesced global
        }
    }
}

// ---------------- 5) tf32 AV: 256q x 64d, 512 threads, double buffered -------
__global__ void __launch_bounds__(512)
av_tf32(const float* __restrict__ P, const float* __restrict__ V, float* __restrict__ O)
{
    extern __shared__ float avsm[];
    float* Ps = avsm;                  // [2][256][68]
    float* Vs = avsm + 2 * 256 * 68;   // [2][64][72]
    int tid = threadIdx.x, w = tid >> 5, l = tid & 31, g = l >> 2, t4 = l & 3;
    int q0 = blockIdx.x * 256;
    int bh = blockIdx.y, b_ = bh >> 2, h = bh & 3;
    int wm = (w >> 1) * 32, wn = (w & 1) * 32;

    float acc[2][4][4];
    #pragma unroll
    for (int i = 0; i < 2; i++)
        #pragma unroll
        for (int j = 0; j < 4; j++)
            #pragma unroll
            for (int e = 0; e < 4; e++) acc[i][j][e] = 0.f;

    const float* Pb_g = P + (size_t)bh * TT * TT;
    const float* Vb_g = V + (size_t)bh * TT * DKK;

    auto load_stage = [&](int buf, int t0) {
        float* Pd = Ps + buf * 256 * 68;
        #pragma unroll
        for (int j = 0; j < 8; j++) {
            int ch = tid + 512 * j;
            int row = ch >> 4, c = ch & 15;
            cpa16(&Pd[row * 68 + c * 4], Pb_g + (size_t)(q0 + row) * TT + t0 + c * 4);
        }
        float* Vd = Vs + buf * 64 * 72;
        #pragma unroll
        for (int j = 0; j < 2; j++) {
            int ch = tid + 512 * j;
            int row = ch >> 4, c = ch & 15;
            cpa16(&Vd[row * 72 + c * 4], Vb_g + (size_t)(t0 + row) * DKK + c * 4);
        }
        cp_commit();
    };

    load_stage(0, 0);

    for (int it = 0; it < 16; it++) {
        int buf = it & 1;
        cp_wait<0>();
        __syncthreads();
        if (it + 1 < 16) load_stage(buf ^ 1, (it + 1) * 64);
        const float* Pd = Ps + buf * 256 * 68;
        const float* Vd = Vs + buf * 64 * 72;
        #pragma unroll
        for (int ks = 0; ks < 8; ks++) {
            unsigned af[2][4], bf[4][2];
            #pragma unroll
            for (int mi = 0; mi < 2; mi++) {
                int r = wm + mi * 16;
                af[mi][0] = f2tf(Pd[(r + g    ) * 68 + ks * 8 + t4]);
                af[mi][1] = f2tf(Pd[(r + g + 8) * 68 + ks * 8 + t4]);
                af[mi][2] = f2tf(Pd[(r + g    ) * 68 + ks * 8 + t4 + 4]);
                af[mi][3] = f2tf(Pd[(r + g + 8) * 68 + ks * 8 + t4 + 4]);
            }
            #pragma unroll
            for (int ni = 0; ni < 4; ni++) {
                int c = wn + ni * 8 + g;
                bf[ni][0] = f2tf(Vd[(ks * 8 + t4    ) * 72 + c]);
                bf[ni][1] = f2tf(Vd[(ks * 8 + t4 + 4) * 72 + c]);
            }
            #pragma unroll
            for (int mi = 0; mi < 2; mi++)
                #pragma unroll
                for (int ni = 0; ni < 4; ni++)
                    mma8(acc[mi][ni], af[mi], bf[ni], acc[mi][ni]);
        }
        __syncthreads();
    }

    #pragma unroll
    for (int mi = 0; mi < 2; mi++)
        #pragma unroll
        for (int ni = 0; ni < 4; ni++) {
            int qq = q0 + wm + mi * 16 + g;
            int d  = wn + ni * 8 + 2 * t4;
            *(float2*)&O[((size_t)b_ * TT + qq) * FF + h * DKK + d] =
                make_float2(acc[mi][ni][0], acc[mi][ni][1]);
            *(float2*)&O[((size_t)b_ * TT + qq + 8) * FF + h * DKK + d] =
                make_float2(acc[mi][ni][2], acc[mi][ni][3]);
        }
}

// ---------------- launch ------------------------------------------------------
extern "C" void kernel_launch(void* const* d_in, const int* in_sizes, int n_in,
                              void* d_out, int out_size)
{
    (void)in_sizes; (void)n_in; (void)out_size;
    const float* x     = (const float*)d_in[0];
    const float* q_in  = (const float*)d_in[1];
    const float* pos_k = (const float*)d_in[2];
    const int*   mask  = (const int*)  d_in[3];
    const float* ln_g  = (const float*)d_in[4];
    const float* ln_b  = (const float*)d_in[5];
    const float* Wq    = (const float*)d_in[6];
    const float* bq    = (const float*)d_in[7];
    const float* Wk    = (const float*)d_in[8];
    const float* bk    = (const float*)d_in[9];
    const float* Wv    = (const float*)d_in[10];
    const float* bv    = (const float*)d_in[11];
    const float* Wo    = (const float*)d_in[12];
    const float* bo    = (const float*)d_in[13];
    float* out = (float*)d_out;

    float *p_xn, *p_q, *p_k, *p_v, *p_s, *p_att;
    cudaGetSymbolAddress((void**)&p_xn,  g_xn);
    cudaGetSymbolAddress((void**)&p_q,   g_q);
    cudaGetSymbolAddress((void**)&p_k,   g_k);
    cudaGetSymbolAddress((void**)&p_v,   g_v);
    cudaGetSymbolAddress((void**)&p_s,   g_s);
    cudaGetSymbolAddress((void**)&p_att, g_att);

    static const int GEMM_SMEM = 3 * G_STAGE_F * 4;
    static const int QK_SMEM   = 2 * 128 * 68 * 4;
    static const int BSM_SMEM  = (32 * SSTR + 32 * 68 + 8 * 1024
                                  + 2 * 64 * 68) * 4;                // 207872
    static const int AV_SMEM   = (2 * 256 * 68 + 2 * 64 * 72) * 4;   // 176128
    cudaFuncSetAttribute(proj3_kernel,    cudaFuncAttributeMaxDynamicSharedMemorySize, GEMM_SMEM);
    cudaFuncSetAttribute(gemm_out_kernel, cudaFuncAttributeMaxDynamicSharedMemorySize, GEMM_SMEM);
    cudaFuncSetAttribute(qk_tf32,         cudaFuncAttributeMaxDynamicSharedMemorySize, QK_SMEM);
    cudaFuncSetAttribute(bsm_kernel,      cudaFuncAttributeMaxDynamicSharedMemorySize, BSM_SMEM);
    cudaFuncSetAttribute(av_tf32,         cudaFuncAttributeMaxDynamicSharedMemorySize, AV_SMEM);

    ln_kernel<<<NROWS, 256>>>(x, ln_g, ln_b, p_xn);

    dim3 gproj(FF / 64, NROWS / 128, 3);
    proj3_kernel<<<gproj, 256, GEMM_SMEM>>>(q_in, p_xn, Wq, bq, Wk, bk, Wv, bv,
                                            p_q, p_k, p_v);

    dim3 gqk(TT / 128, TT / 128, BHH);
    qk_tf32<<<gqk, 256, QK_SMEM>>>(p_q, p_k, p_s);

    bsm_kernel<<<TT, 512, BSM_SMEM>>>(p_q, pos_k, mask, p_s);

    dim3 gav(TT / 256, BHH);
    av_tf32<<<gav, 512, AV_SMEM>>>(p_s, p_v, p_att);

    dim3 gout(FF / 64, NROWS / 128);
    gemm_out_kernel<<<gout, 256, GEMM_SMEM>>>(p_att, Wo, bo, out);
}

// round 14
// speedup vs baseline: 1.2691x; 1.0126x over previous
#include <cuda_runtime.h>
#include <math.h>
#include <float.h>

#define BB    8
#define TT    1024
#define FF    256
#define NH    4
#define DKK   64
#define BHH   32
#define NROWS 8192

#define HT    512    // t-half handled per bsm CTA
#define SST2  516    // Ss row stride (516*4 = 2064 B, 16B-aligned)

// ---------------- scratch ----------------------------------------------------
static __device__ float  g_xn[NROWS * FF];
static __device__ float  g_q [BHH * TT * DKK];
static __device__ float  g_k [BHH * TT * DKK];
static __device__ float  g_v [BHH * TT * DKK];
static __device__ float  g_s [(size_t)BHH * TT * TT];
static __device__ float  g_att[NROWS * FF];
static __device__ float2 g_ms[2 * BHH * TT];   // per (half, bh, q): (max, sum)

// ---------------- helpers -----------------------------------------------------
__device__ __forceinline__ unsigned f2tf(float x) {
    unsigned r; asm("cvt.rna.tf32.f32 %0, %1;" : "=r"(r) : "f"(x)); return r;
}
__device__ __forceinline__ void mma8(float* d, const unsigned* a, const unsigned* b, const float* c) {
    asm volatile("mma.sync.aligned.m16n8k8.row.col.f32.tf32.tf32.f32 "
                 "{%0,%1,%2,%3}, {%4,%5,%6,%7}, {%8,%9}, {%10,%11,%12,%13};"
                 : "=f"(d[0]), "=f"(d[1]), "=f"(d[2]), "=f"(d[3])
                 : "r"(a[0]), "r"(a[1]), "r"(a[2]), "r"(a[3]),
                   "r"(b[0]), "r"(b[1]),
                   "f"(c[0]), "f"(c[1]), "f"(c[2]), "f"(c[3]));
}
__device__ __forceinline__ void cpa16(void* s, const void* g) {
    unsigned a = (unsigned)__cvta_generic_to_shared(s);
    asm volatile("cp.async.cg.shared.global [%0], [%1], 16;" :: "r"(a), "l"(g));
}
__device__ __forceinline__ void cp_commit() { asm volatile("cp.async.commit_group;"); }
template<int N> __device__ __forceinline__ void cp_wait() {
    asm volatile("cp.async.wait_group %0;" :: "n"(N));
}

// ---------------- 1) LayerNorm -----------------------------------------------
__global__ void ln_kernel(const float* __restrict__ x, const float* __restrict__ g,
                          const float* __restrict__ b, float* __restrict__ out)
{
    int row = blockIdx.x;
    int tid = threadIdx.x;
    float v = x[row * FF + tid];
    float s = v, sq = v * v;
    __shared__ float rs[8], rq[8];
    #pragma unroll
    for (int o = 16; o > 0; o >>= 1) {
        s  += __shfl_down_sync(0xffffffffu, s,  o);
        sq += __shfl_down_sync(0xffffffffu, sq, o);
    }
    if ((tid & 31) == 0) { rs[tid >> 5] = s; rq[tid >> 5] = sq; }
    __syncthreads();
    if (tid < 32) {
        float a = (tid < 8) ? rs[tid] : 0.f;
        float c = (tid < 8) ? rq[tid] : 0.f;
        #pragma unroll
        for (int o = 4; o > 0; o >>= 1) {
            a += __shfl_down_sync(0xffffffffu, a, o);
            c += __shfl_down_sync(0xffffffffu, c, o);
        }
        if (tid == 0) { rs[0] = a; rq[0] = c; }
    }
    __syncthreads();
    float mean = rs[0] * (1.f / FF);
    float var  = rq[0] * (1.f / FF) - mean * mean;
    float inv  = rsqrtf(fmaxf(var, 0.f) + 1e-5f);
    out[row * FF + tid] = (v - mean) * inv * g[tid] + b[tid];
}

// ---------------- 2) tf32 GEMM core: 128x64, BK=32, 3-stage cp.async ---------
#define G_STAGE_F (128 * 36 + 32 * 72)

__device__ __forceinline__ void gemm_body(
    const float* __restrict__ A, const float* __restrict__ W,
    const float* __restrict__ bias, float* __restrict__ C, int MODE)
{
    extern __shared__ float gsm[];
    int tid = threadIdx.x, w = tid >> 5, l = tid & 31, g = l >> 2, t4 = l & 3;
    int m0 = blockIdx.y * 128, n0 = blockIdx.x * 64;
    int wm = (w >> 1) * 32, wn = (w & 1) * 32;

    float acc[2][4][4];
    #pragma unroll
    for (int i = 0; i < 2; i++)
        #pragma unroll
        for (int j = 0; j < 4; j++)
            #pragma unroll
            for (int e = 0; e < 4; e++) acc[i][j][e] = 0.f;

    auto load_stage = [&](int s, int k0) {
        float* Ab = gsm + s * G_STAGE_F;
        float* Wb = Ab + 128 * 36;
        #pragma unroll
        for (int j = 0; j < 4; j++) {
            int ch = tid + 256 * j;
            int row = ch >> 3, c = ch & 7;
            cpa16(&Ab[row * 36 + c * 4], A + (size_t)(m0 + row) * FF + k0 + c * 4);
        }
        #pragma unroll
        for (int j = 0; j < 2; j++) {
            int ch = tid + 256 * j;
            int row = ch >> 4, c = ch & 15;
            cpa16(&Wb[row * 72 + c * 4], W + (size_t)(k0 + row) * FF + n0 + c * 4);
        }
        cp_commit();
    };

    load_stage(0, 0);
    load_stage(1, 32);

    for (int it = 0; it < 8; it++) {
        int s = it % 3;
        if (it == 7) cp_wait<0>(); else cp_wait<1>();
        __syncthreads();
        if (it + 2 < 8) load_stage((it + 2) % 3, (it + 2) * 32);
        const float* Ab = gsm + s * G_STAGE_F;
        const float* Wb = Ab + 128 * 36;
        #pragma unroll
        for (int ks = 0; ks < 4; ks++) {
            unsigned af[2][4], bf[4][2];
            #pragma unroll
            for (int mi = 0; mi < 2; mi++) {
                int r = wm + mi * 16;
                af[mi][0] = f2tf(Ab[(r + g    ) * 36 + ks * 8 + t4]);
                af[mi][1] = f2tf(Ab[(r + g + 8) * 36 + ks * 8 + t4]);
                af[mi][2] = f2tf(Ab[(r + g    ) * 36 + ks * 8 + t4 + 4]);
                af[mi][3] = f2tf(Ab[(r + g + 8) * 36 + ks * 8 + t4 + 4]);
            }
            #pragma unroll
            for (int ni = 0; ni < 4; ni++) {
                int c = wn + ni * 8 + g;
                bf[ni][0] = f2tf(Wb[(ks * 8 + t4    ) * 72 + c]);
                bf[ni][1] = f2tf(Wb[(ks * 8 + t4 + 4) * 72 + c]);
            }
            #pragma unroll
            for (int mi = 0; mi < 2; mi++)
                #pragma unroll
                for (int ni = 0; ni < 4; ni++)
                    mma8(acc[mi][ni], af[mi], bf[ni], acc[mi][ni]);
        }
        __syncthreads();
    }

    #pragma unroll
    for (int mi = 0; mi < 2; mi++) {
        #pragma unroll
        for (int ni = 0; ni < 4; ni++) {
            int col = n0 + wn + ni * 8 + 2 * t4;
            float b0 = bias[col], b1 = bias[col + 1];
            int r0 = m0 + wm + mi * 16 + g;
            float2 o0 = make_float2(acc[mi][ni][0] + b0, acc[mi][ni][1] + b1);
            float2 o1 = make_float2(acc[mi][ni][2] + b0, acc[mi][ni][3] + b1);
            if (MODE == 0) {
                int h = col >> 6, d = col & 63;
                int b_ = r0 >> 10, t = r0 & 1023;
                *(float2*)&C[(((size_t)(b_*NH + h) * TT + t) * DKK) + d] = o0;
                int r1 = r0 + 8; b_ = r1 >> 10; t = r1 & 1023;
                *(float2*)&C[(((size_t)(b_*NH + h) * TT + t) * DKK) + d] = o1;
            } else {
                *(float2*)&C[(size_t)r0 * FF + col] = o0;
                *(float2*)&C[(size_t)(r0 + 8) * FF + col] = o1;
            }
        }
    }
}

__global__ void __launch_bounds__(256)
proj3_kernel(const float* __restrict__ Aq, const float* __restrict__ Axn,
             const float* __restrict__ Wq, const float* __restrict__ bq,
             const float* __restrict__ Wk, const float* __restrict__ bk,
             const float* __restrict__ Wv, const float* __restrict__ bv,
             float* __restrict__ Cq, float* __restrict__ Ck, float* __restrict__ Cv)
{
    int z = blockIdx.z;
    const float* A = (z == 0) ? Aq : Axn;
    const float* W = (z == 0) ? Wq : (z == 1) ? Wk : Wv;
    const float* b = (z == 0) ? bq : (z == 1) ? bk : bv;
    float* C       = (z == 0) ? Cq : (z == 1) ? Ck : Cv;
    gemm_body(A, W, b, C, 0);
}

__global__ void __launch_bounds__(256)
gemm_out_kernel(const float* __restrict__ A, const float* __restrict__ W,
                const float* __restrict__ bias, float* __restrict__ C)
{
    gemm_body(A, W, bias, C, 1);
}

// ---------------- 3) tf32 QK^T: 128q x 128t, K=64 ----------------------------
__global__ void __launch_bounds__(256)
qk_tf32(const float* __restrict__ Q, const float* __restrict__ K, float* __restrict__ S)
{
    extern __shared__ float qksm[];
    float* Qs = qksm;             // [128][68]
    float* Ks = qksm + 128 * 68;  // [128][68]
    int tid = threadIdx.x, w = tid >> 5, l = tid & 31, g = l >> 2, t4 = l & 3;
    int bh = blockIdx.z, q0 = blockIdx.y * 128, t0 = blockIdx.x * 128;
    int wm = (w >> 2) * 64, wn = (w & 3) * 32;

    #pragma unroll
    for (int j = 0; j < 8; j++) {
        int ch = tid + 256 * j;
        int row = ch >> 4, c = ch & 15;
        cpa16(&Qs[row * 68 + c * 4], Q + ((size_t)bh * TT + q0 + row) * DKK + c * 4);
    }
    #pragma unroll
    for (int j = 0; j < 8; j++) {
        int ch = tid + 256 * j;
        int row = ch >> 4, c = ch & 15;
        cpa16(&Ks[row * 68 + c * 4], K + ((size_t)bh * TT + t0 + row) * DKK + c * 4);
    }
    cp_commit(); cp_wait<0>();
    __syncthreads();

    float acc[4][4][4];
    #pragma unroll
    for (int i = 0; i < 4; i++)
        #pragma unroll
        for (int j = 0; j < 4; j++)
            #pragma unroll
            for (int e = 0; e < 4; e++) acc[i][j][e] = 0.f;

    #pragma unroll
    for (int ks = 0; ks < 8; ks++) {
        unsigned af[4][4], bf[4][2];
        #pragma unroll
        for (int mi = 0; mi < 4; mi++) {
            int r = wm + mi * 16;
            af[mi][0] = f2tf(Qs[(r + g    ) * 68 + ks * 8 + t4]);
            af[mi][1] = f2tf(Qs[(r + g + 8) * 68 + ks * 8 + t4]);
            af[mi][2] = f2tf(Qs[(r + g    ) * 68 + ks * 8 + t4 + 4]);
            af[mi][3] = f2tf(Qs[(r + g + 8) * 68 + ks * 8 + t4 + 4]);
        }
        #pragma unroll
        for (int ni = 0; ni < 4; ni++) {
            int c = wn + ni * 8 + g;
            bf[ni][0] = f2tf(Ks[c * 68 + ks * 8 + t4]);
            bf[ni][1] = f2tf(Ks[c * 68 + ks * 8 + t4 + 4]);
        }
        #pragma unroll
        for (int mi = 0; mi < 4; mi++)
            #pragma unroll
            for (int ni = 0; ni < 4; ni++)
                mma8(acc[mi][ni], af[mi], bf[ni], acc[mi][ni]);
    }

    float* dst = S + (size_t)bh * TT * TT;
    #pragma unroll
    for (int mi = 0; mi < 4; mi++)
        #pragma unroll
        for (int ni = 0; ni < 4; ni++) {
            int r0 = q0 + wm + mi * 16 + g;
            int col = t0 + wn + ni * 8 + 2 * t4;
            *(float2*)&dst[(size_t)r0 * TT + col] = make_float2(acc[mi][ni][0], acc[mi][ni][1]);
            *(float2*)&dst[(size_t)(r0 + 8) * TT + col] = make_float2(acc[mi][ni][2], acc[mi][ni][3]);
        }
}

// ---------------- 4) bias + mask + PARTIAL softmax (split-t, 2 CTAs/SM) ------
// Grid (2 halves, 1024 q), 512 thr. Phase 1: 8 chunks of 64 t, double-buffered
// pos_k, bias mma into Ss[32][516]. Phase 2: combine with S + mask, local
// max/sum, write unnormalized exp to S and (m,s) to g_ms. AV merges halves.
__global__ void __launch_bounds__(512, 2)
bsm_kernel(const float* __restrict__ Qg, const float* __restrict__ PK,
           const int* __restrict__ mask, float* __restrict__ S,
           float2* __restrict__ gms)
{
    extern __shared__ float sm[];
    float* Ss = sm;                          // [32][516]   66.0 KB
    float* Qs = Ss + 32 * SST2;              // [32][68]     8.7 KB
    float* Ps = Qs + 32 * 68;                // [2][64][68] 34.8 KB  -> 109.5 KB
    int tid = threadIdx.x, w = tid >> 5, l = tid & 31, g = l >> 2, t4 = l & 3;
    int q = blockIdx.y, half = blockIdx.x;
    int tbase = half * HT;
    int wm_ = (w & 1) * 16, wn_ = (w >> 1) * 8;   // 16 warps: 2m x 8n over 64 t

    if (tid < 256) {
        int bh = tid >> 3, dg = (tid & 7) * 8;
        const float* src = Qg + ((size_t)bh * TT + q) * DKK + dg;
        *(float4*)&Qs[bh * 68 + dg]     = *(const float4*)(src);
        *(float4*)&Qs[bh * 68 + dg + 4] = *(const float4*)(src + 4);
    }

    auto load_chunk = [&](int buf, int c) {
        int t0 = tbase + c * 64;
        float* Pb = Ps + buf * 64 * 68;
        #pragma unroll
        for (int j = 0; j < 2; j++) {        // 64 rows x 16 cpa16
            int ch = tid + 512 * j;
            int row = ch >> 4, cc = ch & 15;
            cpa16(&Pb[row * 68 + cc * 4], PK + ((size_t)q * TT + t0 + row) * DKK + cc * 4);
        }
        cp_commit();
    };

    load_chunk(0, 0);
    __syncthreads();                         // Qs visible

    for (int c = 0; c < 8; c++) {
        int buf = c & 1;
        cp_wait<0>();
        __syncthreads();
        if (c + 1 < 8) load_chunk(buf ^ 1, c + 1);
        const float* Pb = Ps + buf * 64 * 68;

        float acc[4] = {0.f, 0.f, 0.f, 0.f};
        #pragma unroll
        for (int ks = 0; ks < 8; ks++) {
            unsigned af[4], bf[2];
            af[0] = f2tf(Qs[(wm_ + g    ) * 68 + ks * 8 + t4]);
            af[1] = f2tf(Qs[(wm_ + g + 8) * 68 + ks * 8 + t4]);
            af[2] = f2tf(Qs[(wm_ + g    ) * 68 + ks * 8 + t4 + 4]);
            af[3] = f2tf(Qs[(wm_ + g + 8) * 68 + ks * 8 + t4 + 4]);
            int cn = wn_ + g;
            bf[0] = f2tf(Pb[cn * 68 + ks * 8 + t4]);
            bf[1] = f2tf(Pb[cn * 68 + ks * 8 + t4 + 4]);
            mma8(acc, af, bf, acc);
        }
        int t0 = c * 64;
        int colL = wn_ + 2 * t4;
        #pragma unroll
        for (int rr = 0; rr < 2; rr++) {
            int bh = wm_ + g + rr * 8;
            *(float2*)&Ss[bh * SST2 + t0 + colL] =
                make_float2(acc[rr * 2], acc[rr * 2 + 1]);
        }
        __syncthreads();
    }

    // ---- phase 2: combine + mask + local softmax stats; warp w: bh=2w,2w+1 --
    #pragma unroll
    for (int bb = 0; bb < 2; bb++) {
        int bh = w * 2 + bb;
        int b_ = bh >> 2;
        float* srow = S + (size_t)bh * TT * TT + (size_t)q * TT + tbase;
        const int* mrow = mask + ((size_t)b_ * TT + q) * TT + tbase;
        float* ssr = Ss + bh * SST2;

        float mx = -FLT_MAX;
        #pragma unroll
        for (int i = 0; i < 4; i++) {
            int t = 4 * (l + 32 * i);
            float4 sv = *(const float4*)&srow[t];   // coalesced global
            int4   mv = *(const int4*)&mrow[t];     // coalesced global
            float4 bv = *(const float4*)&ssr[t];    // smem (bias)
            float4 o;
            o.x = (mv.x == 0) ? -FLT_MAX : (sv.x + bv.x) * 0.125f;
            o.y = (mv.y == 0) ? -FLT_MAX : (sv.y + bv.y) * 0.125f;
            o.z = (mv.z == 0) ? -FLT_MAX : (sv.z + bv.z) * 0.125f;
            o.w = (mv.w == 0) ? -FLT_MAX : (sv.w + bv.w) * 0.125f;
            *(float4*)&ssr[t] = o;
            mx = fmaxf(mx, fmaxf(fmaxf(o.x, o.y), fmaxf(o.z, o.w)));
        }
        #pragma unroll
        for (int o = 16; o > 0; o >>= 1)
            mx = fmaxf(mx, __shfl_xor_sync(0xffffffffu, mx, o));

        float sum = 0.f;
        #pragma unroll
        for (int i = 0; i < 4; i++) {
            int t = 4 * (l + 32 * i);
            float4 v = *(const float4*)&ssr[t];
            float4 p;
            p.x = (v.x == -FLT_MAX) ? 0.f : __expf(v.x - mx);
            p.y = (v.y == -FLT_MAX) ? 0.f : __expf(v.y - mx);
            p.z = (v.z == -FLT_MAX) ? 0.f : __expf(v.z - mx);
            p.w = (v.w == -FLT_MAX) ? 0.f : __expf(v.w - mx);
            sum += p.x + p.y + p.z + p.w;
            *(float4*)&srow[t] = p;                 // unnormalized exp -> global
        }
        #pragma unroll
        for (int o = 16; o > 0; o >>= 1)
            sum += __shfl_xor_sync(0xffffffffu, sum, o);

        if (l == 0)
            gms[((size_t)half * BHH + bh) * TT + q] = make_float2(mx, sum);
    }
}

// ---------------- 5) tf32 AV: 256q x 64d, dual half-accumulators + merge -----
__global__ void __launch_bounds__(512)
av_tf32(const float* __restrict__ P, const float* __restrict__ V,
        const float2* __restrict__ gms, float* __restrict__ O)
{
    extern __shared__ float avsm[];
    float* Ps = avsm;                  // [2][256][68]
    float* Vs = avsm + 2 * 256 * 68;   // [2][64][72]
    int tid = threadIdx.x, w = tid >> 5, l = tid & 31, g = l >> 2, t4 = l & 3;
    int q0 = blockIdx.x * 256;
    int bh = blockIdx.y, b_ = bh >> 2, h = bh & 3;
    int wm = (w >> 1) * 32, wn = (w & 1) * 32;

    float acc[2][2][4][4];   // [t-half][mi][ni][e]
    #pragma unroll
    for (int hf = 0; hf < 2; hf++)
        #pragma unroll
        for (int i = 0; i < 2; i++)
            #pragma unroll
            for (int j = 0; j < 4; j++)
                #pragma unroll
                for (int e = 0; e < 4; e++) acc[hf][i][j][e] = 0.f;

    const float* Pb_g = P + (size_t)bh * TT * TT;
    const float* Vb_g = V + (size_t)bh * TT * DKK;

    auto load_stage = [&](int buf, int t0) {
        float* Pd = Ps + buf * 256 * 68;
        #pragma unroll
        for (int j = 0; j < 8; j++) {
            int ch = tid + 512 * j;
            int row = ch >> 4, c = ch & 15;
            cpa16(&Pd[row * 68 + c * 4], Pb_g + (size_t)(q0 + row) * TT + t0 + c * 4);
        }
        float* Vd = Vs + buf * 64 * 72;
        #pragma unroll
        for (int j = 0; j < 2; j++) {
            int ch = tid + 512 * j;
            int row = ch >> 4, c = ch & 15;
            cpa16(&Vd[row * 72 + c * 4], Vb_g + (size_t)(t0 + row) * DKK + c * 4);
        }
        cp_commit();
    };

    load_stage(0, 0);

    for (int it = 0; it < 16; it++) {
        int buf = it & 1;
        int hf  = it >> 3;
        cp_wait<0>();
        __syncthreads();
        if (it + 1 < 16) load_stage(buf ^ 1, (it + 1) * 64);
        const float* Pd = Ps + buf * 256 * 68;
        const float* Vd = Vs + buf * 64 * 72;
        #pragma unroll
        for (int ks = 0; ks < 8; ks++) {
            unsigned af[2][4], bf[4][2];
            #pragma unroll
            for (int mi = 0; mi < 2; mi++) {
                int r = wm + mi * 16;
                af[mi][0] = f2tf(Pd[(r + g    ) * 68 + ks * 8 + t4]);
                af[mi][1] = f2tf(Pd[(r + g + 8) * 68 + ks * 8 + t4]);
                af[mi][2] = f2tf(Pd[(r + g    ) * 68 + ks * 8 + t4 + 4]);
                af[mi][3] = f2tf(Pd[(r + g + 8) * 68 + ks * 8 + t4 + 4]);
            }
            #pragma unroll
            for (int ni = 0; ni < 4; ni++) {
                int c = wn + ni * 8 + g;
                bf[ni][0] = f2tf(Vd[(ks * 8 + t4    ) * 72 + c]);
                bf[ni][1] = f2tf(Vd[(ks * 8 + t4 + 4) * 72 + c]);
            }
            #pragma unroll
            for (int mi = 0; mi < 2; mi++)
                #pragma unroll
                for (int ni = 0; ni < 4; ni++)
                    mma8(acc[hf][mi][ni], af[mi], bf[ni], acc[hf][mi][ni]);
        }
        __syncthreads();
    }

    // epilogue: merge halves with flash-style scales
    auto scales = [&](int row, float& s0, float& s1) {
        float2 a = gms[(size_t)bh * TT + row];                 // half 0
        float2 b = gms[((size_t)BHH + bh) * TT + row];         // half 1
        float m = fmaxf(a.x, b.x);
        if (m == -FLT_MAX) { s0 = 0.f; s1 = 0.f; return; }
        float w0 = __expf(a.x - m), w1 = __expf(b.x - m);
        float Z = a.y * w0 + b.y * w1;
        float inv = (Z > 0.f) ? (1.f / Z) : 0.f;
        s0 = w0 * inv; s1 = w1 * inv;
    };

    #pragma unroll
    for (int mi = 0; mi < 2; mi++) {
        int qq = q0 + wm + mi * 16 + g;
        float sc0a, sc1a, sc0b, sc1b;
        scales(qq,     sc0a, sc1a);
        scales(qq + 8, sc0b, sc1b);
        #pragma unroll
        for (int ni = 0; ni < 4; ni++) {
            int d = wn + ni * 8 + 2 * t4;
            float2 o0, o1;
            o0.x = acc[0][mi][ni][0] * sc0a + acc[1][mi][ni][0] * sc1a;
            o0.y = acc[0][mi][ni][1] * sc0a + acc[1][mi][ni][1] * sc1a;
            o1.x = acc[0][mi][ni][2] * sc0b + acc[1][mi][ni][2] * sc1b;
            o1.y = acc[0][mi][ni][3] * sc0b + acc[1][mi][ni][3] * sc1b;
            *(float2*)&O[((size_t)b_ * TT + qq) * FF + h * DKK + d] = o0;
            *(float2*)&O[((size_t)b_ * TT + qq + 8) * FF + h * DKK + d] = o1;
        }
    }
}

// ---------------- launch ------------------------------------------------------
extern "C" void kernel_launch(void* const* d_in, const int* in_sizes, int n_in,
                              void* d_out, int out_size)
{
    (void)in_sizes; (void)n_in; (void)out_size;
    const float* x     = (const float*)d_in[0];
    const float* q_in  = (const float*)d_in[1];
    const float* pos_k = (const float*)d_in[2];
    const int*   mask  = (const int*)  d_in[3];
    const float* ln_g  = (const float*)d_in[4];
    const float* ln_b  = (const float*)d_in[5];
    const float* Wq    = (const float*)d_in[6];
    const float* bq    = (const float*)d_in[7];
    const float* Wk    = (const float*)d_in[8];
    const float* bk    = (const float*)d_in[9];
    const float* Wv    = (const float*)d_in[10];
    const float* bv    = (const float*)d_in[11];
    const float* Wo    = (const float*)d_in[12];
    const float* bo    = (const float*)d_in[13];
    float* out = (float*)d_out;

    float *p_xn, *p_q, *p_k, *p_v, *p_s, *p_att;
    float2* p_ms;
    cudaGetSymbolAddress((void**)&p_xn,  g_xn);
    cudaGetSymbolAddress((void**)&p_q,   g_q);
    cudaGetSymbolAddress((void**)&p_k,   g_k);
    cudaGetSymbolAddress((void**)&p_v,   g_v);
    cudaGetSymbolAddress((void**)&p_s,   g_s);
    cudaGetSymbolAddress((void**)&p_att, g_att);
    cudaGetSymbolAddress((void**)&p_ms,  g_ms);

    static const int GEMM_SMEM = 3 * G_STAGE_F * 4;
    static const int QK_SMEM   = 2 * 128 * 68 * 4;
    static const int BSM_SMEM  = (32 * SST2 + 32 * 68 + 2 * 64 * 68) * 4; // 109568
    static const int AV_SMEM   = (2 * 256 * 68 + 2 * 64 * 72) * 4;        // 176128
    cudaFuncSetAttribute(proj3_kernel,    cudaFuncAttributeMaxDynamicSharedMemorySize, GEMM_SMEM);
    cudaFuncSetAttribute(gemm_out_kernel, cudaFuncAttributeMaxDynamicSharedMemorySize, GEMM_SMEM);
    cudaFuncSetAttribute(qk_tf32,         cudaFuncAttributeMaxDynamicSharedMemorySize, QK_SMEM);
    cudaFuncSetAttribute(bsm_kernel,      cudaFuncAttributeMaxDynamicSharedMemorySize, BSM_SMEM);
    cudaFuncSetAttribute(av_tf32,         cudaFuncAttributeMaxDynamicSharedMemorySize, AV_SMEM);

    ln_kernel<<<NROWS, 256>>>(x, ln_g, ln_b, p_xn);

    dim3 gproj(FF / 64, NROWS / 128, 3);
    proj3_kernel<<<gproj, 256, GEMM_SMEM>>>(q_in, p_xn, Wq, bq, Wk, bk, Wv, bv,
                                            p_q, p_k, p_v);

    dim3 gqk(TT / 128, TT / 128, BHH);
    qk_tf32<<<gqk, 256, QK_SMEM>>>(p_q, p_k, p_s);

    dim3 gbsm(2, TT);
    bsm_kernel<<<gbsm, 512, BSM_SMEM>>>(p_q, pos_k, mask, p_s, p_ms);

    dim3 gav(TT / 256, BHH);
    av_tf32<<<gav, 512, AV_SMEM>>>(p_s, p_v, p_ms, p_att);

    dim3 gout(FF / 64, NROWS / 128);
    gemm_out_kernel<<<gout, 256, GEMM_SMEM>>>(p_att, Wo, bo, out);
}

// round 17
// speedup vs baseline: 1.4023x; 1.1050x over previous
#include <cuda_runtime.h>
#include <math.h>
#include <float.h>

#define BB    8
#define TT    1024
#define FF    256
#define NH    4
#define DKK   64
#define BHH   32
#define NROWS 8192

#define HT    512    // t-half handled per bsm CTA
#define SST2  516    // Ss row stride (516*4 = 2064 B, 16B-aligned)

// ---------------- scratch ----------------------------------------------------
static __device__ float  g_xn[NROWS * FF];
static __device__ float  g_q [BHH * TT * DKK];
static __device__ float  g_k [BHH * TT * DKK];
static __device__ float  g_v [BHH * TT * DKK];
static __device__ float  g_s [(size_t)BHH * TT * TT];
static __device__ float  g_att[NROWS * FF];
static __device__ float2 g_ms[2 * BHH * TT];   // per (half, bh, q): (max, sum)

// ---------------- helpers -----------------------------------------------------
__device__ __forceinline__ unsigned f2tf(float x) {
    unsigned r; asm("cvt.rna.tf32.f32 %0, %1;" : "=r"(r) : "f"(x)); return r;
}
__device__ __forceinline__ void mma8(float* d, const unsigned* a, const unsigned* b, const float* c) {
    asm volatile("mma.sync.aligned.m16n8k8.row.col.f32.tf32.tf32.f32 "
                 "{%0,%1,%2,%3}, {%4,%5,%6,%7}, {%8,%9}, {%10,%11,%12,%13};"
                 : "=f"(d[0]), "=f"(d[1]), "=f"(d[2]), "=f"(d[3])
                 : "r"(a[0]), "r"(a[1]), "r"(a[2]), "r"(a[3]),
                   "r"(b[0]), "r"(b[1]),
                   "f"(c[0]), "f"(c[1]), "f"(c[2]), "f"(c[3]));
}
__device__ __forceinline__ void cpa16(void* s, const void* g) {
    unsigned a = (unsigned)__cvta_generic_to_shared(s);
    asm volatile("cp.async.cg.shared.global [%0], [%1], 16;" :: "r"(a), "l"(g));
}
__device__ __forceinline__ void cp_commit() { asm volatile("cp.async.commit_group;"); }
template<int N> __device__ __forceinline__ void cp_wait() {
    asm volatile("cp.async.wait_group %0;" :: "n"(N));
}

// ---------------- 1) LayerNorm -----------------------------------------------
__global__ void ln_kernel(const float* __restrict__ x, const float* __restrict__ g,
                          const float* __restrict__ b, float* __restrict__ out)
{
    int row = blockIdx.x;
    int tid = threadIdx.x;
    float v = x[row * FF + tid];
    float s = v, sq = v * v;
    __shared__ float rs[8], rq[8];
    #pragma unroll
    for (int o = 16; o > 0; o >>= 1) {
        s  += __shfl_down_sync(0xffffffffu, s,  o);
        sq += __shfl_down_sync(0xffffffffu, sq, o);
    }
    if ((tid & 31) == 0) { rs[tid >> 5] = s; rq[tid >> 5] = sq; }
    __syncthreads();
    if (tid < 32) {
        float a = (tid < 8) ? rs[tid] : 0.f;
        float c = (tid < 8) ? rq[tid] : 0.f;
        #pragma unroll
        for (int o = 4; o > 0; o >>= 1) {
            a += __shfl_down_sync(0xffffffffu, a, o);
            c += __shfl_down_sync(0xffffffffu, c, o);
        }
        if (tid == 0) { rs[0] = a; rq[0] = c; }
    }
    __syncthreads();
    float mean = rs[0] * (1.f / FF);
    float var  = rq[0] * (1.f / FF) - mean * mean;
    float inv  = rsqrtf(fmaxf(var, 0.f) + 1e-5f);
    out[row * FF + tid] = (v - mean) * inv * g[tid] + b[tid];
}

// ---------------- 2) tf32 GEMM core: 128x64, BK=32, 3-stage cp.async ---------
#define G_STAGE_F (128 * 36 + 32 * 72)

__device__ __forceinline__ void gemm_body(
    const float* __restrict__ A, const float* __restrict__ W,
    const float* __restrict__ bias, float* __restrict__ C, int MODE)
{
    extern __shared__ float gsm[];
    int tid = threadIdx.x, w = tid >> 5, l = tid & 31, g = l >> 2, t4 = l & 3;
    int m0 = blockIdx.y * 128, n0 = blockIdx.x * 64;
    int wm = (w >> 1) * 32, wn = (w & 1) * 32;

    float acc[2][4][4];
    #pragma unroll
    for (int i = 0; i < 2; i++)
        #pragma unroll
        for (int j = 0; j < 4; j++)
            #pragma unroll
            for (int e = 0; e < 4; e++) acc[i][j][e] = 0.f;

    auto load_stage = [&](int s, int k0) {
        float* Ab = gsm + s * G_STAGE_F;
        float* Wb = Ab + 128 * 36;
        #pragma unroll
        for (int j = 0; j < 4; j++) {
            int ch = tid + 256 * j;
            int row = ch >> 3, c = ch & 7;
            cpa16(&Ab[row * 36 + c * 4], A + (size_t)(m0 + row) * FF + k0 + c * 4);
        }
        #pragma unroll
        for (int j = 0; j < 2; j++) {
            int ch = tid + 256 * j;
            int row = ch >> 4, c = ch & 15;
            cpa16(&Wb[row * 72 + c * 4], W + (size_t)(k0 + row) * FF + n0 + c * 4);
        }
        cp_commit();
    };

    load_stage(0, 0);
    load_stage(1, 32);

    for (int it = 0; it < 8; it++) {
        int s = it % 3;
        if (it == 7) cp_wait<0>(); else cp_wait<1>();
        __syncthreads();
        if (it + 2 < 8) load_stage((it + 2) % 3, (it + 2) * 32);
        const float* Ab = gsm + s * G_STAGE_F;
        const float* Wb = Ab + 128 * 36;
        #pragma unroll
        for (int ks = 0; ks < 4; ks++) {
            unsigned af[2][4], bf[4][2];
            #pragma unroll
            for (int mi = 0; mi < 2; mi++) {
                int r = wm + mi * 16;
                af[mi][0] = f2tf(Ab[(r + g    ) * 36 + ks * 8 + t4]);
                af[mi][1] = f2tf(Ab[(r + g + 8) * 36 + ks * 8 + t4]);
                af[mi][2] = f2tf(Ab[(r + g    ) * 36 + ks * 8 + t4 + 4]);
                af[mi][3] = f2tf(Ab[(r + g + 8) * 36 + ks * 8 + t4 + 4]);
            }
            #pragma unroll
            for (int ni = 0; ni < 4; ni++) {
                int c = wn + ni * 8 + g;
                bf[ni][0] = f2tf(Wb[(ks * 8 + t4    ) * 72 + c]);
                bf[ni][1] = f2tf(Wb[(ks * 8 + t4 + 4) * 72 + c]);
            }
            #pragma unroll
            for (int mi = 0; mi < 2; mi++)
                #pragma unroll
                for (int ni = 0; ni < 4; ni++)
                    mma8(acc[mi][ni], af[mi], bf[ni], acc[mi][ni]);
        }
        __syncthreads();
    }

    #pragma unroll
    for (int mi = 0; mi < 2; mi++) {
        #pragma unroll
        for (int ni = 0; ni < 4; ni++) {
            int col = n0 + wn + ni * 8 + 2 * t4;
            float b0 = bias[col], b1 = bias[col + 1];
            int r0 = m0 + wm + mi * 16 + g;
            float2 o0 = make_float2(acc[mi][ni][0] + b0, acc[mi][ni][1] + b1);
            float2 o1 = make_float2(acc[mi][ni][2] + b0, acc[mi][ni][3] + b1);
            if (MODE == 0) {
                int h = col >> 6, d = col & 63;
                int b_ = r0 >> 10, t = r0 & 1023;
                *(float2*)&C[(((size_t)(b_*NH + h) * TT + t) * DKK) + d] = o0;
                int r1 = r0 + 8; b_ = r1 >> 10; t = r1 & 1023;
                *(float2*)&C[(((size_t)(b_*NH + h) * TT + t) * DKK) + d] = o1;
            } else {
                *(float2*)&C[(size_t)r0 * FF + col] = o0;
                *(float2*)&C[(size_t)(r0 + 8) * FF + col] = o1;
            }
        }
    }
}

__global__ void __launch_bounds__(256)
proj3_kernel(const float* __restrict__ Aq, const float* __restrict__ Axn,
             const float* __restrict__ Wq, const float* __restrict__ bq,
             const float* __restrict__ Wk, const float* __restrict__ bk,
             const float* __restrict__ Wv, const float* __restrict__ bv,
             float* __restrict__ Cq, float* __restrict__ Ck, float* __restrict__ Cv)
{
    int z = blockIdx.z;
    const float* A = (z == 0) ? Aq : Axn;
    const float* W = (z == 0) ? Wq : (z == 1) ? Wk : Wv;
    const float* b = (z == 0) ? bq : (z == 1) ? bk : bv;
    float* C       = (z == 0) ? Cq : (z == 1) ? Ck : Cv;
    gemm_body(A, W, b, C, 0);
}

__global__ void __launch_bounds__(256)
gemm_out_kernel(const float* __restrict__ A, const float* __restrict__ W,
                const float* __restrict__ bias, float* __restrict__ C)
{
    gemm_body(A, W, bias, C, 1);
}

// ---------------- 3) tf32 QK^T: 128q x 128t, K=64 ----------------------------
__global__ void __launch_bounds__(256)
qk_tf32(const float* __restrict__ Q, const float* __restrict__ K, float* __restrict__ S)
{
    extern __shared__ float qksm[];
    float* Qs = qksm;             // [128][68]
    float* Ks = qksm + 128 * 68;  // [128][68]
    int tid = threadIdx.x, w = tid >> 5, l = tid & 31, g = l >> 2, t4 = l & 3;
    int bh = blockIdx.z, q0 = blockIdx.y * 128, t0 = blockIdx.x * 128;
    int wm = (w >> 2) * 64, wn = (w & 3) * 32;

    #pragma unroll
    for (int j = 0; j < 8; j++) {
        int ch = tid + 256 * j;
        int row = ch >> 4, c = ch & 15;
        cpa16(&Qs[row * 68 + c * 4], Q + ((size_t)bh * TT + q0 + row) * DKK + c * 4);
    }
    #pragma unroll
    for (int j = 0; j < 8; j++) {
        int ch = tid + 256 * j;
        int row = ch >> 4, c = ch & 15;
        cpa16(&Ks[row * 68 + c * 4], K + ((size_t)bh * TT + t0 + row) * DKK + c * 4);
    }
    cp_commit(); cp_wait<0>();
    __syncthreads();

    float acc[4][4][4];
    #pragma unroll
    for (int i = 0; i < 4; i++)
        #pragma unroll
        for (int j = 0; j < 4; j++)
            #pragma unroll
            for (int e = 0; e < 4; e++) acc[i][j][e] = 0.f;

    #pragma unroll
    for (int ks = 0; ks < 8; ks++) {
        unsigned af[4][4], bf[4][2];
        #pragma unroll
        for (int mi = 0; mi < 4; mi++) {
            int r = wm + mi * 16;
            af[mi][0] = f2tf(Qs[(r + g    ) * 68 + ks * 8 + t4]);
            af[mi][1] = f2tf(Qs[(r + g + 8) * 68 + ks * 8 + t4]);
            af[mi][2] = f2tf(Qs[(r + g    ) * 68 + ks * 8 + t4 + 4]);
            af[mi][3] = f2tf(Qs[(r + g + 8) * 68 + ks * 8 + t4 + 4]);
        }
        #pragma unroll
        for (int ni = 0; ni < 4; ni++) {
            int c = wn + ni * 8 + g;
            bf[ni][0] = f2tf(Ks[c * 68 + ks * 8 + t4]);
            bf[ni][1] = f2tf(Ks[c * 68 + ks * 8 + t4 + 4]);
        }
        #pragma unroll
        for (int mi = 0; mi < 4; mi++)
            #pragma unroll
            for (int ni = 0; ni < 4; ni++)
                mma8(acc[mi][ni], af[mi], bf[ni], acc[mi][ni]);
    }

    float* dst = S + (size_t)bh * TT * TT;
    #pragma unroll
    for (int mi = 0; mi < 4; mi++)
        #pragma unroll
        for (int ni = 0; ni < 4; ni++) {
            int r0 = q0 + wm + mi * 16 + g;
            int col = t0 + wn + ni * 8 + 2 * t4;
            *(float2*)&dst[(size_t)r0 * TT + col] = make_float2(acc[mi][ni][0], acc[mi][ni][1]);
            *(float2*)&dst[(size_t)(r0 + 8) * TT + col] = make_float2(acc[mi][ni][2], acc[mi][ni][3]);
        }
}

// ---------------- 4) bias + mask + PARTIAL softmax (split-t, 2 CTAs/SM) ------
// Grid (2 halves, 1024 q), 512 thr. Phase 1: 8 chunks of 64 t, double-buffered
// pos_k, bias mma into Ss[32][516]. Phase 2: combine with S + mask, local
// max/sum, write unnormalized exp to S and (m,s) to g_ms. AV merges halves.
__global__ void __launch_bounds__(512, 2)
bsm_kernel(const float* __restrict__ Qg, const float* __restrict__ PK,
           const int* __restrict__ mask, float* __restrict__ S,
           float2* __restrict__ gms)
{
    extern __shared__ float sm[];
    float* Ss = sm;                          // [32][516]   66.0 KB
    float* Qs = Ss + 32 * SST2;              // [32][68]     8.7 KB
    float* Ps = Qs + 32 * 68;                // [2][64][68] 34.8 KB  -> 109.5 KB
    int tid = threadIdx.x, w = tid >> 5, l = tid & 31, g = l >> 2, t4 = l & 3;
    int q = blockIdx.y, half = blockIdx.x;
    int tbase = half * HT;
    int wm_ = (w & 1) * 16, wn_ = (w >> 1) * 8;   // 16 warps: 2m x 8n over 64 t

    if (tid < 256) {
        int bh = tid >> 3, dg = (tid & 7) * 8;
        const float* src = Qg + ((size_t)bh * TT + q) * DKK + dg;
        *(float4*)&Qs[bh * 68 + dg]     = *(const float4*)(src);
        *(float4*)&Qs[bh * 68 + dg + 4] = *(const float4*)(src + 4);
    }

    auto load_chunk = [&](int buf, int c) {
        int t0 = tbase + c * 64;
        float* Pb = Ps + buf * 64 * 68;
        #pragma unroll
        for (int j = 0; j < 2; j++) {        // 64 rows x 16 cpa16
            int ch = tid + 512 * j;
            int row = ch >> 4, cc = ch & 15;
            cpa16(&Pb[row * 68 + cc * 4], PK + ((size_t)q * TT + t0 + row) * DKK + cc * 4);
        }
        cp_commit();
    };

    load_chunk(0, 0);
    __syncthreads();                         // Qs visible

    for (int c = 0; c < 8; c++) {
        int buf = c & 1;
        cp_wait<0>();
        __syncthreads();
        if (c + 1 < 8) load_chunk(buf ^ 1, c + 1);
        const float* Pb = Ps + buf * 64 * 68;

        float acc[4] = {0.f, 0.f, 0.f, 0.f};
        #pragma unroll
        for (int ks = 0; ks < 8; ks++) {
            unsigned af[4], bf[2];
            af[0] = f2tf(Qs[(wm_ + g    ) * 68 + ks * 8 + t4]);
            af[1] = f2tf(Qs[(wm_ + g + 8) * 68 + ks * 8 + t4]);
            af[2] = f2tf(Qs[(wm_ + g    ) * 68 + ks * 8 + t4 + 4]);
            af[3] = f2tf(Qs[(wm_ + g + 8) * 68 + ks * 8 + t4 + 4]);
            int cn = wn_ + g;
            bf[0] = f2tf(Pb[cn * 68 + ks * 8 + t4]);
            bf[1] = f2tf(Pb[cn * 68 + ks * 8 + t4 + 4]);
            mma8(acc, af, bf, acc);
        }
        int t0 = c * 64;
        int colL = wn_ + 2 * t4;
        #pragma unroll
        for (int rr = 0; rr < 2; rr++) {
            int bh = wm_ + g + rr * 8;
            *(float2*)&Ss[bh * SST2 + t0 + colL] =
                make_float2(acc[rr * 2], acc[rr * 2 + 1]);
        }
        __syncthreads();
    }

    // ---- phase 2: combine + mask + local softmax stats; warp w: bh=2w,2w+1 --
    #pragma unroll
    for (int bb = 0; bb < 2; bb++) {
        int bh = w * 2 + bb;
        int b_ = bh >> 2;
        float* srow = S + (size_t)bh * TT * TT + (size_t)q * TT + tbase;
        const int* mrow = mask + ((size_t)b_ * TT + q) * TT + tbase;
        float* ssr = Ss + bh * SST2;

        float mx = -FLT_MAX;
        #pragma unroll
        for (int i = 0; i < 4; i++) {
            int t = 4 * (l + 32 * i);
            float4 sv = *(const float4*)&srow[t];   // coalesced global
            int4   mv = *(const int4*)&mrow[t];     // coalesced global
            float4 bv = *(const float4*)&ssr[t];    // smem (bias)
            float4 o;
            o.x = (mv.x == 0) ? -FLT_MAX : (sv.x + bv.x) * 0.125f;
            o.y = (mv.y == 0) ? -FLT_MAX : (sv.y + bv.y) * 0.125f;
            o.z = (mv.z == 0) ? -FLT_MAX : (sv.z + bv.z) * 0.125f;
            o.w = (mv.w == 0) ? -FLT_MAX : (sv.w + bv.w) * 0.125f;
            *(float4*)&ssr[t] = o;
            mx = fmaxf(mx, fmaxf(fmaxf(o.x, o.y), fmaxf(o.z, o.w)));
        }
        #pragma unroll
        for (int o = 16; o > 0; o >>= 1)
            mx = fmaxf(mx, __shfl_xor_sync(0xffffffffu, mx, o));

        float sum = 0.f;
        #pragma unroll
        for (int i = 0; i < 4; i++) {
            int t = 4 * (l + 32 * i);
            float4 v = *(const float4*)&ssr[t];
            float4 p;
            p.x = (v.x == -FLT_MAX) ? 0.f : __expf(v.x - mx);
            p.y = (v.y == -FLT_MAX) ? 0.f : __expf(v.y - mx);
            p.z = (v.z == -FLT_MAX) ? 0.f : __expf(v.z - mx);
            p.w = (v.w == -FLT_MAX) ? 0.f : __expf(v.w - mx);
            sum += p.x + p.y + p.z + p.w;
            *(float4*)&srow[t] = p;                 // unnormalized exp -> global
        }
        #pragma unroll
        for (int o = 16; o > 0; o >>= 1)
            sum += __shfl_xor_sync(0xffffffffu, sum, o);

        if (l == 0)
            gms[((size_t)half * BHH + bh) * TT + q] = make_float2(mx, sum);
    }
}

// ---------------- 5) tf32 AV: 256q x 64d, single accumulator -----------------
// Flash merge folded into the mainloop: P fragments are pre-scaled by the
// per-(row, t-half) factor sc_hf = exp(m_hf - m) / Z before tf32 conversion,
// so one 32-reg accumulator produces the final normalized output directly.
__global__ void __launch_bounds__(512)
av_tf32(const float* __restrict__ P, const float* __restrict__ V,
        const float2* __restrict__ gms, float* __restrict__ O)
{
    extern __shared__ float avsm[];
    float* Ps = avsm;                  // [2][256][68]
    float* Vs = avsm + 2 * 256 * 68;   // [2][64][72]
    int tid = threadIdx.x, w = tid >> 5, l = tid & 31, g = l >> 2, t4 = l & 3;
    int q0 = blockIdx.x * 256;
    int bh = blockIdx.y, b_ = bh >> 2, h = bh & 3;
    int wm = (w >> 1) * 32, wn = (w & 1) * 32;

    // per-thread scales: scl[half][mi][rowpair]
    float scl[2][2][2];
    #pragma unroll
    for (int mi = 0; mi < 2; mi++)
        #pragma unroll
        for (int rp = 0; rp < 2; rp++) {
            int row = q0 + wm + mi * 16 + g + rp * 8;
            float2 a = gms[(size_t)bh * TT + row];
            float2 b = gms[((size_t)BHH + bh) * TT + row];
            float m = fmaxf(a.x, b.x);
            float s0 = 0.f, s1 = 0.f;
            if (m != -FLT_MAX) {
                float w0 = __expf(a.x - m), w1 = __expf(b.x - m);
                float Z = a.y * w0 + b.y * w1;
                float inv = (Z > 0.f) ? (1.f / Z) : 0.f;
                s0 = w0 * inv; s1 = w1 * inv;
            }
            scl[0][mi][rp] = s0;
            scl[1][mi][rp] = s1;
        }

    float acc[2][4][4];
    #pragma unroll
    for (int i = 0; i < 2; i++)
        #pragma unroll
        for (int j = 0; j < 4; j++)
            #pragma unroll
            for (int e = 0; e < 4; e++) acc[i][j][e] = 0.f;

    const float* Pb_g = P + (size_t)bh * TT * TT;
    const float* Vb_g = V + (size_t)bh * TT * DKK;

    auto load_stage = [&](int buf, int t0) {
        float* Pd = Ps + buf * 256 * 68;
        #pragma unroll
        for (int j = 0; j < 8; j++) {
            int ch = tid + 512 * j;
            int row = ch >> 4, c = ch & 15;
            cpa16(&Pd[row * 68 + c * 4], Pb_g + (size_t)(q0 + row) * TT + t0 + c * 4);
        }
        float* Vd = Vs + buf * 64 * 72;
        #pragma unroll
        for (int j = 0; j < 2; j++) {
            int ch = tid + 512 * j;
            int row = ch >> 4, c = ch & 15;
            cpa16(&Vd[row * 72 + c * 4], Vb_g + (size_t)(t0 + row) * DKK + c * 4);
        }
        cp_commit();
    };

    load_stage(0, 0);

    for (int it = 0; it < 16; it++) {
        int buf = it & 1;
        int hf  = it >> 3;
        cp_wait<0>();
        __syncthreads();
        if (it + 1 < 16) load_stage(buf ^ 1, (it + 1) * 64);
        const float* Pd = Ps + buf * 256 * 68;
        const float* Vd = Vs + buf * 64 * 72;
        #pragma unroll
        for (int ks = 0; ks < 8; ks++) {
            unsigned af[2][4], bf[4][2];
            #pragma unroll
            for (int mi = 0; mi < 2; mi++) {
                int r = wm + mi * 16;
                af[mi][0] = f2tf(Pd[(r + g    ) * 68 + ks * 8 + t4]     * scl[hf][mi][0]);
                af[mi][1] = f2tf(Pd[(r + g + 8) * 68 + ks * 8 + t4]     * scl[hf][mi][1]);
                af[mi][2] = f2tf(Pd[(r + g    ) * 68 + ks * 8 + t4 + 4] * scl[hf][mi][0]);
                af[mi][3] = f2tf(Pd[(r + g + 8) * 68 + ks * 8 + t4 + 4] * scl[hf][mi][1]);
            }
            #pragma unroll
            for (int ni = 0; ni < 4; ni++) {
                int c = wn + ni * 8 + g;
                bf[ni][0] = f2tf(Vd[(ks * 8 + t4    ) * 72 + c]);
                bf[ni][1] = f2tf(Vd[(ks * 8 + t4 + 4) * 72 + c]);
            }
            #pragma unroll
            for (int mi = 0; mi < 2; mi++)
                #pragma unroll
                for (int ni = 0; ni < 4; ni++)
                    mma8(acc[mi][ni], af[mi], bf[ni], acc[mi][ni]);
        }
        __syncthreads();
    }

    #pragma unroll
    for (int mi = 0; mi < 2; mi++) {
        int qq = q0 + wm + mi * 16 + g;
        #pragma unroll
        for (int ni = 0; ni < 4; ni++) {
            int d = wn + ni * 8 + 2 * t4;
            *(float2*)&O[((size_t)b_ * TT + qq) * FF + h * DKK + d] =
                make_float2(acc[mi][ni][0], acc[mi][ni][1]);
            *(float2*)&O[((size_t)b_ * TT + qq + 8) * FF + h * DKK + d] =
                make_float2(acc[mi][ni][2], acc[mi][ni][3]);
        }
    }
}

// ---------------- launch ------------------------------------------------------
extern "C" void kernel_launch(void* const* d_in, const int* in_sizes, int n_in,
                              void* d_out, int out_size)
{
    (void)in_sizes; (void)n_in; (void)out_size;
    const float* x     = (const float*)d_in[0];
    const float* q_in  = (const float*)d_in[1];
    const float* pos_k = (const float*)d_in[2];
    const int*   mask  = (const int*)  d_in[3];
    const float* ln_g  = (const float*)d_in[4];
    const float* ln_b  = (const float*)d_in[5];
    const float* Wq    = (const float*)d_in[6];
    const float* bq    = (const float*)d_in[7];
    const float* Wk    = (const float*)d_in[8];
    const float* bk    = (const float*)d_in[9];
    const float* Wv    = (const float*)d_in[10];
    const float* bv    = (const float*)d_in[11];
    const float* Wo    = (const float*)d_in[12];
    const float* bo    = (const float*)d_in[13];
    float* out = (float*)d_out;

    float *p_xn, *p_q, *p_k, *p_v, *p_s, *p_att;
    float2* p_ms;
    cudaGetSymbolAddress((void**)&p_xn,  g_xn);
    cudaGetSymbolAddress((void**)&p_q,   g_q);
    cudaGetSymbolAddress((void**)&p_k,   g_k);
    cudaGetSymbolAddress((void**)&p_v,   g_v);
    cudaGetSymbolAddress((void**)&p_s,   g_s);
    cudaGetSymbolAddress((void**)&p_att, g_att);
    cudaGetSymbolAddress((void**)&p_ms,  g_ms);

    static const int GEMM_SMEM = 3 * G_STAGE_F * 4;
    static const int QK_SMEM   = 2 * 128 * 68 * 4;
    static const int BSM_SMEM  = (32 * SST2 + 32 * 68 + 2 * 64 * 68) * 4; // 109568
    static const int AV_SMEM   = (2 * 256 * 68 + 2 * 64 * 72) * 4;        // 176128
    cudaFuncSetAttribute(proj3_kernel,    cudaFuncAttributeMaxDynamicSharedMemorySize, GEMM_SMEM);
    cudaFuncSetAttribute(gemm_out_kernel, cudaFuncAttributeMaxDynamicSharedMemorySize, GEMM_SMEM);
    cudaFuncSetAttribute(qk_tf32,         cudaFuncAttributeMaxDynamicSharedMemorySize, QK_SMEM);
    cudaFuncSetAttribute(bsm_kernel,      cudaFuncAttributeMaxDynamicSharedMemorySize, BSM_SMEM);
    cudaFuncSetAttribute(av_tf32,         cudaFuncAttributeMaxDynamicSharedMemorySize, AV_SMEM);

    ln_kernel<<<NROWS, 256>>>(x, ln_g, ln_b, p_xn);

    dim3 gproj(FF / 64, NROWS / 128, 3);
    proj3_kernel<<<gproj, 256, GEMM_SMEM>>>(q_in, p_xn, Wq, bq, Wk, bk, Wv, bv,
                                            p_q, p_k, p_v);

    dim3 gqk(TT / 128, TT / 128, BHH);
    qk_tf32<<<gqk, 256, QK_SMEM>>>(p_q, p_k, p_s);

    dim3 gbsm(2, TT);
    bsm_kernel<<<gbsm, 512, BSM_SMEM>>>(p_q, pos_k, mask, p_s, p_ms);

    dim3 gav(TT / 256, BHH);
    av_tf32<<<gav, 512, AV_SMEM>>>(p_s, p_v, p_ms, p_att);

    dim3 gout(FF / 64, NROWS / 128);
    gemm_out_kernel<<<gout, 256, GEMM_SMEM>>>(p_att, Wo, bo, out);
}